// round 6
// baseline (speedup 1.0000x reference)
#include <cuda_runtime.h>
#include <cstdint>

#define Bb 4
#define Mm 256
#define Tt 64
#define BT 256      // B*T
#define KD 512      // 2M == D_MOT == D_ABS
#define DOUT 768
#define JSPLIT 4
#define KSPLIT 2
#define PSZ (3*BT*KD)   // one stage1 partial plane (768 x 512)

// Scratch (no allocation allowed -> __device__ globals)
__device__ float d_V [Mm*BT];              // V [j][bt]
__device__ float d_VX[Mm*BT];
__device__ float d_VY[Mm*BT];
__device__ float d_S1p[JSPLIT*PSZ];        // stage1 partials
__device__ float d_cvp[KSPLIT*DOUT];       // cvec partials (fcoutb folded into plane 0)
__device__ float d_S2p[KSPLIT*1024*DOUT];  // stage2 partials (rows 0..767 A, 768..1023 base)

__device__ __forceinline__ bool is_nan_bits(float x) {
    return (__float_as_uint(x) & 0x7fffffffu) > 0x7f800000u;
}

// ---------------------------------------------------------------------------
// prep: build V/VX/VY in (j, bt) layout.  grid=(256 j), block=256 (bt)
// ---------------------------------------------------------------------------
__global__ void prep_kernel(const float* __restrict__ coords,
                            const float* __restrict__ vis) {
    int j = blockIdx.x;
    int t = threadIdx.x;           // bt = b*64 + tt
    int b = t >> 6, tt = t & 63;
    int idx = (b*Mm + j)*Tt + tt;
    float2 xy = ((const float2*)coords)[idx];
    float v = vis[idx];
    float x = xy.x, y = xy.y;
    if (is_nan_bits(x)) { v = 0.f; x = 0.f; }
    if (is_nan_bits(y)) { y = 0.f; }
    int o = j*BT + t;
    d_V [o] = v;
    d_VX[o] = x * v;
    d_VY[o] = y * v;
}

// ---------------------------------------------------------------------------
// stage1: S0 = V@We, S1 = V@Wo, SU = VX@We + VY@Wo   (contraction over j)
// grid=(4 bt-tiles x64, 8 k-tiles x64, JSPLIT j-splits x64), block=256
// writes JSPLIT partial planes; stage2 sums them while loading.
// ---------------------------------------------------------------------------
__global__ void stage1_kernel(const float* __restrict__ fc1w) {
    __shared__ float Vt [16][64], VXt[16][64], VYt[16][64];
    __shared__ float W0t[16][64], W1t[16][64];
    int bt0 = blockIdx.x * 64;
    int k0  = blockIdx.y * 64;
    int js  = blockIdx.z;
    int jb  = js * 64;
    int t  = threadIdx.x;
    int tx = t & 15;       // k quad
    int ty = t >> 4;       // bt quad
    float s0[4][4], s1[4][4], su[4][4];
    #pragma unroll
    for (int i = 0; i < 4; i++)
        #pragma unroll
        for (int j = 0; j < 4; j++) { s0[i][j]=0.f; s1[i][j]=0.f; su[i][j]=0.f; }

    int lj = t >> 4;           // load row 0..15
    int lc = (t & 15) * 4;     // load col quad

    for (int jc = 0; jc < 64; jc += 16) {
        int jrow = jb + jc + lj;
        *(float4*)&Vt [lj][lc] = *(const float4*)&d_V [jrow*BT + bt0 + lc];
        *(float4*)&VXt[lj][lc] = *(const float4*)&d_VX[jrow*BT + bt0 + lc];
        *(float4*)&VYt[lj][lc] = *(const float4*)&d_VY[jrow*BT + bt0 + lc];
        *(float4*)&W0t[lj][lc] = *(const float4*)&fc1w[(2*jrow  )*KD + k0 + lc];
        *(float4*)&W1t[lj][lc] = *(const float4*)&fc1w[(2*jrow+1)*KD + k0 + lc];
        __syncthreads();
        #pragma unroll
        for (int kk = 0; kk < 16; kk++) {
            float4 v4 = *(const float4*)&Vt [kk][ty*4];
            float4 x4 = *(const float4*)&VXt[kk][ty*4];
            float4 y4 = *(const float4*)&VYt[kk][ty*4];
            float4 w0 = *(const float4*)&W0t[kk][tx*4];
            float4 w1 = *(const float4*)&W1t[kk][tx*4];
            float vv[4] = {v4.x,v4.y,v4.z,v4.w};
            float xx[4] = {x4.x,x4.y,x4.z,x4.w};
            float yy[4] = {y4.x,y4.y,y4.z,y4.w};
            float a0[4] = {w0.x,w0.y,w0.z,w0.w};
            float a1[4] = {w1.x,w1.y,w1.z,w1.w};
            #pragma unroll
            for (int i = 0; i < 4; i++)
                #pragma unroll
                for (int j = 0; j < 4; j++) {
                    s0[i][j] = fmaf(vv[i], a0[j], s0[i][j]);
                    s1[i][j] = fmaf(vv[i], a1[j], s1[i][j]);
                    su[i][j] = fmaf(xx[i], a0[j], fmaf(yy[i], a1[j], su[i][j]));
                }
        }
        __syncthreads();
    }
    float* base = d_S1p + (size_t)js*PSZ;
    #pragma unroll
    for (int i = 0; i < 4; i++) {
        int bt = bt0 + ty*4 + i;
        int k  = k0 + tx*4;
        *(float4*)&base[(0*BT + bt)*KD + k] = make_float4(s0[i][0],s0[i][1],s0[i][2],s0[i][3]);
        *(float4*)&base[(1*BT + bt)*KD + k] = make_float4(s1[i][0],s1[i][1],s1[i][2],s1[i][3]);
        *(float4*)&base[(2*BT + bt)*KD + k] = make_float4(su[i][0],su[i][1],su[i][2],su[i][3]);
    }
}

// ---------------------------------------------------------------------------
// stage2 (fused combine1 + cvec): C (1024 x 768), K = 512, split-K = 2
//   rows    0..767 : A = sum of 4 stage1 partial planes, B = W2_top
//   rows 768..1023 : A = pos, B = W2_bot
// by==0 blocks additionally compute cvec partial = fc1b @ W2_top slice
// and write d_cvp[bz] (+fcoutb on bz=0).
// grid=(12 n x64, 16 m x64, 2 ksplit), block=128, microtile 8x4
// ---------------------------------------------------------------------------
__global__ void stage2_kernel(const float* __restrict__ fcoutw,
                              const float* __restrict__ pos,
                              const float* __restrict__ fc1b,
                              const float* __restrict__ fcoutb) {
    __shared__ float At[16][64];
    __shared__ float Bt[16][64];
    __shared__ float fb[16];
    int bx = blockIdx.x;           // n tile
    int by = blockIdx.y;           // m tile
    int bz = blockIdx.z;           // k split
    bool isBase = (by >= 12);
    bool doCvec = (by == 0);       // stages W2_top -> correct weights for cvec
    const float* Ap = isBase ? (pos + (by-12)*64*KD) : nullptr;
    const float* Bp = fcoutw + (isBase ? KD*DOUT : 0) + bx*64;
    int t  = threadIdx.x;
    int tx = t & 15;    // 4 cols
    int ty = t >> 4;    // 8 rows
    float acc[8][4];
    #pragma unroll
    for (int i = 0; i < 8; i++)
        #pragma unroll
        for (int j = 0; j < 4; j++) acc[i][j] = 0.f;
    float accC[4] = {0.f, 0.f, 0.f, 0.f};

    int arow = t >> 1;          // 0..63
    int koff = (t & 1) * 8;
    int bk   = t >> 4;          // 0..7 (and +8)
    int bn   = (t & 15) * 4;

    int kend = bz*256 + 256;
    for (int kc = bz*256; kc < kend; kc += 16) {
        float4 a0, a1;
        if (isBase) {
            a0 = *(const float4*)&Ap[arow*KD + kc + koff];
            a1 = *(const float4*)&Ap[arow*KD + kc + koff + 4];
        } else {
            const float* rp = d_S1p + (size_t)(by*64 + arow)*KD + kc + koff;
            float4 q0 = *(const float4*)(rp);
            float4 q1 = *(const float4*)(rp + PSZ);
            float4 q2 = *(const float4*)(rp + 2*PSZ);
            float4 q3 = *(const float4*)(rp + 3*PSZ);
            a0 = make_float4((q0.x+q1.x)+(q2.x+q3.x), (q0.y+q1.y)+(q2.y+q3.y),
                             (q0.z+q1.z)+(q2.z+q3.z), (q0.w+q1.w)+(q2.w+q3.w));
            q0 = *(const float4*)(rp + 4);
            q1 = *(const float4*)(rp + PSZ + 4);
            q2 = *(const float4*)(rp + 2*PSZ + 4);
            q3 = *(const float4*)(rp + 3*PSZ + 4);
            a1 = make_float4((q0.x+q1.x)+(q2.x+q3.x), (q0.y+q1.y)+(q2.y+q3.y),
                             (q0.z+q1.z)+(q2.z+q3.z), (q0.w+q1.w)+(q2.w+q3.w));
        }
        if (doCvec && t < 16) fb[t] = fc1b[kc + t];
        At[koff+0][arow] = a0.x; At[koff+1][arow] = a0.y;
        At[koff+2][arow] = a0.z; At[koff+3][arow] = a0.w;
        At[koff+4][arow] = a1.x; At[koff+5][arow] = a1.y;
        At[koff+6][arow] = a1.z; At[koff+7][arow] = a1.w;
        *(float4*)&Bt[bk  ][bn] = *(const float4*)&Bp[(kc+bk  )*DOUT + bn];
        *(float4*)&Bt[bk+8][bn] = *(const float4*)&Bp[(kc+bk+8)*DOUT + bn];
        __syncthreads();
        #pragma unroll
        for (int kk = 0; kk < 16; kk++) {
            float4 b4 = *(const float4*)&Bt[kk][tx*4];
            float4 aA = *(const float4*)&At[kk][ty*8];
            float4 aB = *(const float4*)&At[kk][ty*8 + 4];
            float av[8] = {aA.x,aA.y,aA.z,aA.w,aB.x,aB.y,aB.z,aB.w};
            float bv[4] = {b4.x,b4.y,b4.z,b4.w};
            if (doCvec) {
                float fbv = fb[kk];
                #pragma unroll
                for (int j = 0; j < 4; j++)
                    accC[j] = fmaf(fbv, bv[j], accC[j]);
            }
            #pragma unroll
            for (int i = 0; i < 8; i++)
                #pragma unroll
                for (int j = 0; j < 4; j++)
                    acc[i][j] = fmaf(av[i], bv[j], acc[i][j]);
        }
        __syncthreads();
    }

    int row0 = by*64 + ty*8;
    int col  = bx*64 + tx*4;
    if (doCvec && ty == 0) {
        if (bz == 0) {
            accC[0] += fcoutb[col];   accC[1] += fcoutb[col+1];
            accC[2] += fcoutb[col+2]; accC[3] += fcoutb[col+3];
        }
        *(float4*)&d_cvp[bz*DOUT + col] =
            make_float4(accC[0], accC[1], accC[2], accC[3]);
    }
    float* outp = d_S2p + (size_t)bz*1024*DOUT;
    #pragma unroll
    for (int i = 0; i < 8; i++)
        *(float4*)&outp[(row0+i)*DOUT + col] =
            make_float4(acc[i][0],acc[i][1],acc[i][2],acc[i][3]);
}

// ---------------------------------------------------------------------------
// epilogue: out[bt,m,o] = VX*A0 + VY*A1 - V*AU + base[m,o] + cvec[o]
// (A*/base are sums of KSPLIT stage2 planes; cvec = sum of KSPLIT cvp planes)
// grid=(64 bt-quads, 8 m-tiles x32), block=192 (one float4 column each)
// smem 38.4 KB -> ~5 blocks/SM resident (latency hiding for L2 base stream)
// ---------------------------------------------------------------------------
#define EPI_BT 4
__global__ void epilogue_kernel(float* __restrict__ out) {
    __shared__ float4 A0s[EPI_BT][192], A1s[EPI_BT][192], AUs[EPI_BT][192];
    __shared__ float sV[32][EPI_BT], sVX[32][EPI_BT], sVY[32][EPI_BT];

    int bt0 = blockIdx.x * EPI_BT;
    int m0  = blockIdx.y * 32;
    int t   = threadIdx.x;     // 0..191

    const float4* p0 = (const float4*)d_S2p;
    const float4* p1 = (const float4*)(d_S2p + (size_t)1024*DOUT);

    #pragma unroll
    for (int i = 0; i < EPI_BT; i++) {
        int r0 = (0*BT + bt0+i)*(DOUT/4) + t;
        int r1 = (1*BT + bt0+i)*(DOUT/4) + t;
        int r2 = (2*BT + bt0+i)*(DOUT/4) + t;
        float4 a = p0[r0], b = p1[r0];
        A0s[i][t] = make_float4(a.x+b.x, a.y+b.y, a.z+b.z, a.w+b.w);
        a = p0[r1]; b = p1[r1];
        A1s[i][t] = make_float4(a.x+b.x, a.y+b.y, a.z+b.z, a.w+b.w);
        a = p0[r2]; b = p1[r2];
        AUs[i][t] = make_float4(a.x+b.x, a.y+b.y, a.z+b.z, a.w+b.w);
    }
    if (t < 32*EPI_BT) {
        int mm = t >> 2, bi = t & 3;
        int src = (m0+mm)*BT + bt0 + bi;
        sV [mm][bi] = d_V [src];
        sVX[mm][bi] = d_VX[src];
        sVY[mm][bi] = d_VY[src];
    }
    // cvec column = sum of KSPLIT cvp planes
    float4 cv;
    {
        const float4* cp = (const float4*)d_cvp;
        float4 c0 = cp[t], c1 = cp[(DOUT/4) + t];
        cv = make_float4(c0.x+c1.x, c0.y+c1.y, c0.z+c1.z, c0.w+c1.w);
    }
    __syncthreads();

    #pragma unroll 2
    for (int mm = 0; mm < 32; mm++) {
        int m = m0 + mm;
        int br = (768 + m)*(DOUT/4) + t;
        float4 b0 = p0[br], b1 = p1[br];
        float4 base = make_float4(b0.x+b1.x+cv.x, b0.y+b1.y+cv.y,
                                  b0.z+b1.z+cv.z, b0.w+b1.w+cv.w);
        #pragma unroll
        for (int i = 0; i < EPI_BT; i++) {
            float v  = sV [mm][i];
            float vx = sVX[mm][i];
            float vy = sVY[mm][i];
            float4 a0 = A0s[i][t], a1 = A1s[i][t], au = AUs[i][t];
            float4 o4;
            o4.x = fmaf(vx, a0.x, fmaf(vy, a1.x, fmaf(-v, au.x, base.x)));
            o4.y = fmaf(vx, a0.y, fmaf(vy, a1.y, fmaf(-v, au.y, base.y)));
            o4.z = fmaf(vx, a0.z, fmaf(vy, a1.z, fmaf(-v, au.z, base.z)));
            o4.w = fmaf(vx, a0.w, fmaf(vy, a1.w, fmaf(-v, au.w, base.w)));
            ((float4*)out)[((bt0+i)*Mm + m)*(DOUT/4) + t] = o4;
        }
    }
}

// ---------------------------------------------------------------------------
extern "C" void kernel_launch(void* const* d_in, const int* in_sizes, int n_in,
                              void* d_out, int out_size) {
    const float* coords = (const float*)d_in[0];
    const float* vis    = (const float*)d_in[1];
    const float* pos    = (const float*)d_in[2];
    const float* fc1w   = (const float*)d_in[3];
    const float* fc1b   = (const float*)d_in[4];
    const float* fcoutw = (const float*)d_in[5];
    const float* fcoutb = (const float*)d_in[6];
    float* out = (float*)d_out;

    prep_kernel    <<<Mm, 256>>>(coords, vis);
    stage1_kernel  <<<dim3(4,8,JSPLIT), 256>>>(fc1w);
    stage2_kernel  <<<dim3(12,16,KSPLIT), 128>>>(fcoutw, pos, fc1b, fcoutb);
    epilogue_kernel<<<dim3(BT/EPI_BT,8), 192>>>(out);
}

// round 7
// speedup vs baseline: 1.0805x; 1.0805x over previous
#include <cuda_runtime.h>
#include <cstdint>

#define Bb 4
#define Mm 256
#define Tt 64
#define BT 256      // B*T
#define KD 512      // 2M == D_MOT == D_ABS
#define DOUT 768
#define NF4 (DOUT/4)   // 192 float4 per row
#define JSPLIT 4
#define KSPLIT 2
#define PSZ (3*BT*KD)   // one stage1 partial plane (768 x 512)

// Scratch (no allocation allowed -> __device__ globals)
__device__ float d_V [Mm*BT];              // V [j][bt]
__device__ float d_VX[Mm*BT];
__device__ float d_VY[Mm*BT];
__device__ float d_S1p[JSPLIT*PSZ];        // stage1 partials
__device__ float d_cvp[KSPLIT*DOUT];       // cvec partials (fcoutb folded into plane 0)
__device__ float d_S2p[KSPLIT*1024*DOUT];  // stage2 partials (rows 0..767 A, 768..1023 base)

__device__ __forceinline__ bool is_nan_bits(float x) {
    return (__float_as_uint(x) & 0x7fffffffu) > 0x7f800000u;
}

// ---------------------------------------------------------------------------
// prep: build V/VX/VY in (j, bt) layout.  grid=(256 j), block=256 (bt)
// ---------------------------------------------------------------------------
__global__ void prep_kernel(const float* __restrict__ coords,
                            const float* __restrict__ vis) {
    int j = blockIdx.x;
    int t = threadIdx.x;           // bt = b*64 + tt
    int b = t >> 6, tt = t & 63;
    int idx = (b*Mm + j)*Tt + tt;
    float2 xy = ((const float2*)coords)[idx];
    float v = vis[idx];
    float x = xy.x, y = xy.y;
    if (is_nan_bits(x)) { v = 0.f; x = 0.f; }
    if (is_nan_bits(y)) { y = 0.f; }
    int o = j*BT + t;
    d_V [o] = v;
    d_VX[o] = x * v;
    d_VY[o] = y * v;
}

// ---------------------------------------------------------------------------
// stage1: S0 = V@We, S1 = V@Wo, SU = VX@We + VY@Wo   (contraction over j)
// grid=(4 bt-tiles x64, 8 k-tiles x64, JSPLIT j-splits x64), block=256
// ---------------------------------------------------------------------------
__global__ void stage1_kernel(const float* __restrict__ fc1w) {
    __shared__ float Vt [16][64], VXt[16][64], VYt[16][64];
    __shared__ float W0t[16][64], W1t[16][64];
    int bt0 = blockIdx.x * 64;
    int k0  = blockIdx.y * 64;
    int js  = blockIdx.z;
    int jb  = js * 64;
    int t  = threadIdx.x;
    int tx = t & 15;       // k quad
    int ty = t >> 4;       // bt quad
    float s0[4][4], s1[4][4], su[4][4];
    #pragma unroll
    for (int i = 0; i < 4; i++)
        #pragma unroll
        for (int j = 0; j < 4; j++) { s0[i][j]=0.f; s1[i][j]=0.f; su[i][j]=0.f; }

    int lj = t >> 4;           // load row 0..15
    int lc = (t & 15) * 4;     // load col quad

    for (int jc = 0; jc < 64; jc += 16) {
        int jrow = jb + jc + lj;
        *(float4*)&Vt [lj][lc] = *(const float4*)&d_V [jrow*BT + bt0 + lc];
        *(float4*)&VXt[lj][lc] = *(const float4*)&d_VX[jrow*BT + bt0 + lc];
        *(float4*)&VYt[lj][lc] = *(const float4*)&d_VY[jrow*BT + bt0 + lc];
        *(float4*)&W0t[lj][lc] = *(const float4*)&fc1w[(2*jrow  )*KD + k0 + lc];
        *(float4*)&W1t[lj][lc] = *(const float4*)&fc1w[(2*jrow+1)*KD + k0 + lc];
        __syncthreads();
        #pragma unroll
        for (int kk = 0; kk < 16; kk++) {
            float4 v4 = *(const float4*)&Vt [kk][ty*4];
            float4 x4 = *(const float4*)&VXt[kk][ty*4];
            float4 y4 = *(const float4*)&VYt[kk][ty*4];
            float4 w0 = *(const float4*)&W0t[kk][tx*4];
            float4 w1 = *(const float4*)&W1t[kk][tx*4];
            float vv[4] = {v4.x,v4.y,v4.z,v4.w};
            float xx[4] = {x4.x,x4.y,x4.z,x4.w};
            float yy[4] = {y4.x,y4.y,y4.z,y4.w};
            float a0[4] = {w0.x,w0.y,w0.z,w0.w};
            float a1[4] = {w1.x,w1.y,w1.z,w1.w};
            #pragma unroll
            for (int i = 0; i < 4; i++)
                #pragma unroll
                for (int j = 0; j < 4; j++) {
                    s0[i][j] = fmaf(vv[i], a0[j], s0[i][j]);
                    s1[i][j] = fmaf(vv[i], a1[j], s1[i][j]);
                    su[i][j] = fmaf(xx[i], a0[j], fmaf(yy[i], a1[j], su[i][j]));
                }
        }
        __syncthreads();
    }
    float* base = d_S1p + (size_t)js*PSZ;
    #pragma unroll
    for (int i = 0; i < 4; i++) {
        int bt = bt0 + ty*4 + i;
        int k  = k0 + tx*4;
        *(float4*)&base[(0*BT + bt)*KD + k] = make_float4(s0[i][0],s0[i][1],s0[i][2],s0[i][3]);
        *(float4*)&base[(1*BT + bt)*KD + k] = make_float4(s1[i][0],s1[i][1],s1[i][2],s1[i][3]);
        *(float4*)&base[(2*BT + bt)*KD + k] = make_float4(su[i][0],su[i][1],su[i][2],su[i][3]);
    }
}

// ---------------------------------------------------------------------------
// stage2 (fused combine1 + cvec): C (1024 x 768), K = 512, split-K = 2
//   rows    0..767 : A = sum of 4 stage1 partial planes, B = W2_top
//   rows 768..1023 : A = pos, B = W2_bot
// by==0 blocks additionally compute cvec partial = fc1b @ W2_top slice
// and write d_cvp[bz] (+fcoutb on bz=0).
// grid=(12 n x64, 16 m x64, 2 ksplit), block=128, microtile 8x4
// ---------------------------------------------------------------------------
__global__ void stage2_kernel(const float* __restrict__ fcoutw,
                              const float* __restrict__ pos,
                              const float* __restrict__ fc1b,
                              const float* __restrict__ fcoutb) {
    __shared__ float At[16][64];
    __shared__ float Bt[16][64];
    __shared__ float fb[16];
    int bx = blockIdx.x;           // n tile
    int by = blockIdx.y;           // m tile
    int bz = blockIdx.z;           // k split
    bool isBase = (by >= 12);
    bool doCvec = (by == 0);       // stages W2_top -> correct weights for cvec
    const float* Ap = isBase ? (pos + (by-12)*64*KD) : nullptr;
    const float* Bp = fcoutw + (isBase ? KD*DOUT : 0) + bx*64;
    int t  = threadIdx.x;
    int tx = t & 15;    // 4 cols
    int ty = t >> 4;    // 8 rows
    float acc[8][4];
    #pragma unroll
    for (int i = 0; i < 8; i++)
        #pragma unroll
        for (int j = 0; j < 4; j++) acc[i][j] = 0.f;
    float accC[4] = {0.f, 0.f, 0.f, 0.f};

    int arow = t >> 1;          // 0..63
    int koff = (t & 1) * 8;
    int bk   = t >> 4;          // 0..7 (and +8)
    int bn   = (t & 15) * 4;

    int kend = bz*256 + 256;
    for (int kc = bz*256; kc < kend; kc += 16) {
        float4 a0, a1;
        if (isBase) {
            a0 = *(const float4*)&Ap[arow*KD + kc + koff];
            a1 = *(const float4*)&Ap[arow*KD + kc + koff + 4];
        } else {
            const float* rp = d_S1p + (size_t)(by*64 + arow)*KD + kc + koff;
            float4 q0 = *(const float4*)(rp);
            float4 q1 = *(const float4*)(rp + PSZ);
            float4 q2 = *(const float4*)(rp + 2*PSZ);
            float4 q3 = *(const float4*)(rp + 3*PSZ);
            a0 = make_float4((q0.x+q1.x)+(q2.x+q3.x), (q0.y+q1.y)+(q2.y+q3.y),
                             (q0.z+q1.z)+(q2.z+q3.z), (q0.w+q1.w)+(q2.w+q3.w));
            q0 = *(const float4*)(rp + 4);
            q1 = *(const float4*)(rp + PSZ + 4);
            q2 = *(const float4*)(rp + 2*PSZ + 4);
            q3 = *(const float4*)(rp + 3*PSZ + 4);
            a1 = make_float4((q0.x+q1.x)+(q2.x+q3.x), (q0.y+q1.y)+(q2.y+q3.y),
                             (q0.z+q1.z)+(q2.z+q3.z), (q0.w+q1.w)+(q2.w+q3.w));
        }
        if (doCvec && t < 16) fb[t] = fc1b[kc + t];
        At[koff+0][arow] = a0.x; At[koff+1][arow] = a0.y;
        At[koff+2][arow] = a0.z; At[koff+3][arow] = a0.w;
        At[koff+4][arow] = a1.x; At[koff+5][arow] = a1.y;
        At[koff+6][arow] = a1.z; At[koff+7][arow] = a1.w;
        *(float4*)&Bt[bk  ][bn] = *(const float4*)&Bp[(kc+bk  )*DOUT + bn];
        *(float4*)&Bt[bk+8][bn] = *(const float4*)&Bp[(kc+bk+8)*DOUT + bn];
        __syncthreads();
        #pragma unroll
        for (int kk = 0; kk < 16; kk++) {
            float4 b4 = *(const float4*)&Bt[kk][tx*4];
            float4 aA = *(const float4*)&At[kk][ty*8];
            float4 aB = *(const float4*)&At[kk][ty*8 + 4];
            float av[8] = {aA.x,aA.y,aA.z,aA.w,aB.x,aB.y,aB.z,aB.w};
            float bv[4] = {b4.x,b4.y,b4.z,b4.w};
            if (doCvec) {
                float fbv = fb[kk];
                #pragma unroll
                for (int j = 0; j < 4; j++)
                    accC[j] = fmaf(fbv, bv[j], accC[j]);
            }
            #pragma unroll
            for (int i = 0; i < 8; i++)
                #pragma unroll
                for (int j = 0; j < 4; j++)
                    acc[i][j] = fmaf(av[i], bv[j], acc[i][j]);
        }
        __syncthreads();
    }

    int row0 = by*64 + ty*8;
    int col  = bx*64 + tx*4;
    if (doCvec && ty == 0) {
        if (bz == 0) {
            accC[0] += fcoutb[col];   accC[1] += fcoutb[col+1];
            accC[2] += fcoutb[col+2]; accC[3] += fcoutb[col+3];
        }
        *(float4*)&d_cvp[bz*DOUT + col] =
            make_float4(accC[0], accC[1], accC[2], accC[3]);
    }
    float* outp = d_S2p + (size_t)bz*1024*DOUT;
    #pragma unroll
    for (int i = 0; i < 8; i++)
        *(float4*)&outp[(row0+i)*DOUT + col] =
            make_float4(acc[i][0],acc[i][1],acc[i][2],acc[i][3]);
}

// ---------------------------------------------------------------------------
// epilogue: out[bt,m,o] = VX*A0 + VY*A1 - V*AU + base[m,o] (+cvec folded)
// Block = 4 bt x 32 m x 768 o.  Prologue stages EVERYTHING:
//   - base tile (ksplit planes + cvec summed) -> 98 KB dynamic smem
//   - A rows for 4 bt -> 48 registers/thread
//   - V/VX/VY packed as float4 per (m,bt) -> smem
// Store loop then has ZERO global loads: LDS + FFMA + STG only.
// grid=(64 bt-quads, 8 m-tiles x32), block=192 (one float4 column each)
// ---------------------------------------------------------------------------
#define EPI_BT 4
#define EPI_M  32
__global__ void epilogue_kernel(float* __restrict__ out) {
    extern __shared__ float4 sm[];
    float4* sBase = sm;                    // [EPI_M][192]
    float4* sVp   = sm + EPI_M*NF4;        // [EPI_M][EPI_BT] (vx, vy, v, 0)

    int bt0 = blockIdx.x * EPI_BT;
    int m0  = blockIdx.y * EPI_M;
    int t   = threadIdx.x;     // 0..191

    const float4* p0 = (const float4*)d_S2p;
    const float4* p1 = (const float4*)(d_S2p + (size_t)1024*DOUT);

    // cvec column = sum of KSPLIT cvp planes
    float4 cv;
    {
        const float4* cp = (const float4*)d_cvp;
        float4 c0 = cp[t], c1 = cp[NF4 + t];
        cv = make_float4(c0.x+c1.x, c0.y+c1.y, c0.z+c1.z, c0.w+c1.w);
    }
    // stage base tile: summed planes + cvec (64 independent LDG.128)
    #pragma unroll 4
    for (int mm = 0; mm < EPI_M; mm++) {
        int br = (768 + m0 + mm)*NF4 + t;
        float4 u = p0[br], w = p1[br];
        sBase[mm*NF4 + t] = make_float4(u.x+w.x+cv.x, u.y+w.y+cv.y,
                                        u.z+w.z+cv.z, u.w+w.w+cv.w);
    }
    // A rows for this thread's column, 4 bt, planes summed -> registers
    float4 a0[EPI_BT], a1[EPI_BT], au[EPI_BT];
    #pragma unroll
    for (int i = 0; i < EPI_BT; i++) {
        int r0 = (0*BT + bt0+i)*NF4 + t;
        int r1 = (1*BT + bt0+i)*NF4 + t;
        int r2 = (2*BT + bt0+i)*NF4 + t;
        float4 u, w;
        u = p0[r0]; w = p1[r0]; a0[i] = make_float4(u.x+w.x,u.y+w.y,u.z+w.z,u.w+w.w);
        u = p0[r1]; w = p1[r1]; a1[i] = make_float4(u.x+w.x,u.y+w.y,u.z+w.z,u.w+w.w);
        u = p0[r2]; w = p1[r2]; au[i] = make_float4(u.x+w.x,u.y+w.y,u.z+w.z,u.w+w.w);
    }
    // V scalars packed: sVp[mm*EPI_BT+i] = (vx, vy, v, 0)
    if (t < EPI_M*EPI_BT) {
        int mm = t >> 2, bi = t & 3;
        int src = (m0+mm)*BT + bt0 + bi;
        sVp[mm*EPI_BT + bi] = make_float4(d_VX[src], d_VY[src], d_V[src], 0.f);
    }
    __syncthreads();

    // pure streaming store loop: 5 LDS.128 + 48 FFMA + 4 STG.128 per mm
    #pragma unroll 2
    for (int mm = 0; mm < EPI_M; mm++) {
        float4 bv = sBase[mm*NF4 + t];
        int m = m0 + mm;
        #pragma unroll
        for (int i = 0; i < EPI_BT; i++) {
            float4 vp = sVp[mm*EPI_BT + i];
            float4 o4;
            o4.x = fmaf(vp.x, a0[i].x, fmaf(vp.y, a1[i].x, fmaf(-vp.z, au[i].x, bv.x)));
            o4.y = fmaf(vp.x, a0[i].y, fmaf(vp.y, a1[i].y, fmaf(-vp.z, au[i].y, bv.y)));
            o4.z = fmaf(vp.x, a0[i].z, fmaf(vp.y, a1[i].z, fmaf(-vp.z, au[i].z, bv.z)));
            o4.w = fmaf(vp.x, a0[i].w, fmaf(vp.y, a1[i].w, fmaf(-vp.z, au[i].w, bv.w)));
            ((float4*)out)[((bt0+i)*Mm + m)*NF4 + t] = o4;
        }
    }
}

// ---------------------------------------------------------------------------
extern "C" void kernel_launch(void* const* d_in, const int* in_sizes, int n_in,
                              void* d_out, int out_size) {
    const float* coords = (const float*)d_in[0];
    const float* vis    = (const float*)d_in[1];
    const float* pos    = (const float*)d_in[2];
    const float* fc1w   = (const float*)d_in[3];
    const float* fc1b   = (const float*)d_in[4];
    const float* fcoutw = (const float*)d_in[5];
    const float* fcoutb = (const float*)d_in[6];
    float* out = (float*)d_out;

    static int smem_set = 0;
    int epi_smem = EPI_M*NF4*16 + EPI_M*EPI_BT*16;   // 98304 + 2048 = 100,352 B
    if (!smem_set) {
        cudaFuncSetAttribute(epilogue_kernel,
                             cudaFuncAttributeMaxDynamicSharedMemorySize, epi_smem);
        smem_set = 1;
    }

    prep_kernel    <<<Mm, 256>>>(coords, vis);
    stage1_kernel  <<<dim3(4,8,JSPLIT), 256>>>(fc1w);
    stage2_kernel  <<<dim3(12,16,KSPLIT), 128>>>(fcoutw, pos, fc1b, fcoutb);
    epilogue_kernel<<<dim3(BT/EPI_BT,8), 192, epi_smem>>>(out);
}

// round 8
// speedup vs baseline: 1.1158x; 1.0326x over previous
#include <cuda_runtime.h>
#include <cstdint>

#define Bb 4
#define Mm 256
#define Tt 64
#define BT 256      // B*T
#define KD 512      // 2M == D_MOT == D_ABS
#define DOUT 768
#define NF4 (DOUT/4)   // 192 float4 per row
#define JSPLIT 4
#define KSPLIT 2
#define PSZ (3*BT*KD)   // one stage1 partial plane (768 x 512)

// Scratch (no allocation allowed -> __device__ globals)
__device__ float d_V [Mm*BT];              // V [j][bt]
__device__ float d_VX[Mm*BT];
__device__ float d_VY[Mm*BT];
__device__ float d_S1p[JSPLIT*PSZ];        // stage1 partials
__device__ float d_cvp[KSPLIT*DOUT];       // cvec partials (fcoutb folded into plane 0)
__device__ float d_S2p[KSPLIT*1024*DOUT];  // stage2 partials (rows 0..767 A, 768..1023 base)

__device__ __forceinline__ bool is_nan_bits(float x) {
    return (__float_as_uint(x) & 0x7fffffffu) > 0x7f800000u;
}

// ---------------------------------------------------------------------------
// prep: build V/VX/VY in (j, bt) layout.  grid=(256 j), block=256 (bt)
// ---------------------------------------------------------------------------
__global__ void prep_kernel(const float* __restrict__ coords,
                            const float* __restrict__ vis) {
    int j = blockIdx.x;
    int t = threadIdx.x;           // bt = b*64 + tt
    int b = t >> 6, tt = t & 63;
    int idx = (b*Mm + j)*Tt + tt;
    float2 xy = ((const float2*)coords)[idx];
    float v = vis[idx];
    float x = xy.x, y = xy.y;
    if (is_nan_bits(x)) { v = 0.f; x = 0.f; }
    if (is_nan_bits(y)) { y = 0.f; }
    int o = j*BT + t;
    d_V [o] = v;
    d_VX[o] = x * v;
    d_VY[o] = y * v;
}

// ---------------------------------------------------------------------------
// stage1: S0 = V@We, S1 = V@Wo, SU = VX@We + VY@Wo   (contraction over j)
// grid=(4 bt-tiles x64, 8 k-tiles x64, JSPLIT j-splits x64), block=256
// ---------------------------------------------------------------------------
__global__ void stage1_kernel(const float* __restrict__ fc1w) {
    __shared__ float Vt [16][64], VXt[16][64], VYt[16][64];
    __shared__ float W0t[16][64], W1t[16][64];
    int bt0 = blockIdx.x * 64;
    int k0  = blockIdx.y * 64;
    int js  = blockIdx.z;
    int jb  = js * 64;
    int t  = threadIdx.x;
    int tx = t & 15;       // k quad
    int ty = t >> 4;       // bt quad
    float s0[4][4], s1[4][4], su[4][4];
    #pragma unroll
    for (int i = 0; i < 4; i++)
        #pragma unroll
        for (int j = 0; j < 4; j++) { s0[i][j]=0.f; s1[i][j]=0.f; su[i][j]=0.f; }

    int lj = t >> 4;           // load row 0..15
    int lc = (t & 15) * 4;     // load col quad

    for (int jc = 0; jc < 64; jc += 16) {
        int jrow = jb + jc + lj;
        *(float4*)&Vt [lj][lc] = *(const float4*)&d_V [jrow*BT + bt0 + lc];
        *(float4*)&VXt[lj][lc] = *(const float4*)&d_VX[jrow*BT + bt0 + lc];
        *(float4*)&VYt[lj][lc] = *(const float4*)&d_VY[jrow*BT + bt0 + lc];
        *(float4*)&W0t[lj][lc] = *(const float4*)&fc1w[(2*jrow  )*KD + k0 + lc];
        *(float4*)&W1t[lj][lc] = *(const float4*)&fc1w[(2*jrow+1)*KD + k0 + lc];
        __syncthreads();
        #pragma unroll
        for (int kk = 0; kk < 16; kk++) {
            float4 v4 = *(const float4*)&Vt [kk][ty*4];
            float4 x4 = *(const float4*)&VXt[kk][ty*4];
            float4 y4 = *(const float4*)&VYt[kk][ty*4];
            float4 w0 = *(const float4*)&W0t[kk][tx*4];
            float4 w1 = *(const float4*)&W1t[kk][tx*4];
            float vv[4] = {v4.x,v4.y,v4.z,v4.w};
            float xx[4] = {x4.x,x4.y,x4.z,x4.w};
            float yy[4] = {y4.x,y4.y,y4.z,y4.w};
            float a0[4] = {w0.x,w0.y,w0.z,w0.w};
            float a1[4] = {w1.x,w1.y,w1.z,w1.w};
            #pragma unroll
            for (int i = 0; i < 4; i++)
                #pragma unroll
                for (int j = 0; j < 4; j++) {
                    s0[i][j] = fmaf(vv[i], a0[j], s0[i][j]);
                    s1[i][j] = fmaf(vv[i], a1[j], s1[i][j]);
                    su[i][j] = fmaf(xx[i], a0[j], fmaf(yy[i], a1[j], su[i][j]));
                }
        }
        __syncthreads();
    }
    float* base = d_S1p + (size_t)js*PSZ;
    #pragma unroll
    for (int i = 0; i < 4; i++) {
        int bt = bt0 + ty*4 + i;
        int k  = k0 + tx*4;
        *(float4*)&base[(0*BT + bt)*KD + k] = make_float4(s0[i][0],s0[i][1],s0[i][2],s0[i][3]);
        *(float4*)&base[(1*BT + bt)*KD + k] = make_float4(s1[i][0],s1[i][1],s1[i][2],s1[i][3]);
        *(float4*)&base[(2*BT + bt)*KD + k] = make_float4(su[i][0],su[i][1],su[i][2],su[i][3]);
    }
}

// ---------------------------------------------------------------------------
// stage2 (fused combine1 + cvec): C (1024 x 768), K = 512, split-K = 2
//   rows    0..767 : A = sum of 4 stage1 partial planes, B = W2_top
//   rows 768..1023 : A = pos, B = W2_bot
// by==0 blocks additionally compute cvec partial = fc1b @ W2_top slice
// and write d_cvp[bz] (+fcoutb on bz=0).
// grid=(12 n x64, 16 m x64, 2 ksplit), block=128, microtile 8x4
// ---------------------------------------------------------------------------
__global__ void stage2_kernel(const float* __restrict__ fcoutw,
                              const float* __restrict__ pos,
                              const float* __restrict__ fc1b,
                              const float* __restrict__ fcoutb) {
    __shared__ float At[16][64];
    __shared__ float Bt[16][64];
    __shared__ float fb[16];
    int bx = blockIdx.x;           // n tile
    int by = blockIdx.y;           // m tile
    int bz = blockIdx.z;           // k split
    bool isBase = (by >= 12);
    bool doCvec = (by == 0);       // stages W2_top -> correct weights for cvec
    const float* Ap = isBase ? (pos + (by-12)*64*KD) : nullptr;
    const float* Bp = fcoutw + (isBase ? KD*DOUT : 0) + bx*64;
    int t  = threadIdx.x;
    int tx = t & 15;    // 4 cols
    int ty = t >> 4;    // 8 rows
    float acc[8][4];
    #pragma unroll
    for (int i = 0; i < 8; i++)
        #pragma unroll
        for (int j = 0; j < 4; j++) acc[i][j] = 0.f;
    float accC[4] = {0.f, 0.f, 0.f, 0.f};

    int arow = t >> 1;          // 0..63
    int koff = (t & 1) * 8;
    int bk   = t >> 4;          // 0..7 (and +8)
    int bn   = (t & 15) * 4;

    int kend = bz*256 + 256;
    for (int kc = bz*256; kc < kend; kc += 16) {
        float4 a0, a1;
        if (isBase) {
            a0 = *(const float4*)&Ap[arow*KD + kc + koff];
            a1 = *(const float4*)&Ap[arow*KD + kc + koff + 4];
        } else {
            const float* rp = d_S1p + (size_t)(by*64 + arow)*KD + kc + koff;
            float4 q0 = *(const float4*)(rp);
            float4 q1 = *(const float4*)(rp + PSZ);
            float4 q2 = *(const float4*)(rp + 2*PSZ);
            float4 q3 = *(const float4*)(rp + 3*PSZ);
            a0 = make_float4((q0.x+q1.x)+(q2.x+q3.x), (q0.y+q1.y)+(q2.y+q3.y),
                             (q0.z+q1.z)+(q2.z+q3.z), (q0.w+q1.w)+(q2.w+q3.w));
            q0 = *(const float4*)(rp + 4);
            q1 = *(const float4*)(rp + PSZ + 4);
            q2 = *(const float4*)(rp + 2*PSZ + 4);
            q3 = *(const float4*)(rp + 3*PSZ + 4);
            a1 = make_float4((q0.x+q1.x)+(q2.x+q3.x), (q0.y+q1.y)+(q2.y+q3.y),
                             (q0.z+q1.z)+(q2.z+q3.z), (q0.w+q1.w)+(q2.w+q3.w));
        }
        if (doCvec && t < 16) fb[t] = fc1b[kc + t];
        At[koff+0][arow] = a0.x; At[koff+1][arow] = a0.y;
        At[koff+2][arow] = a0.z; At[koff+3][arow] = a0.w;
        At[koff+4][arow] = a1.x; At[koff+5][arow] = a1.y;
        At[koff+6][arow] = a1.z; At[koff+7][arow] = a1.w;
        *(float4*)&Bt[bk  ][bn] = *(const float4*)&Bp[(kc+bk  )*DOUT + bn];
        *(float4*)&Bt[bk+8][bn] = *(const float4*)&Bp[(kc+bk+8)*DOUT + bn];
        __syncthreads();
        #pragma unroll
        for (int kk = 0; kk < 16; kk++) {
            float4 b4 = *(const float4*)&Bt[kk][tx*4];
            float4 aA = *(const float4*)&At[kk][ty*8];
            float4 aB = *(const float4*)&At[kk][ty*8 + 4];
            float av[8] = {aA.x,aA.y,aA.z,aA.w,aB.x,aB.y,aB.z,aB.w};
            float bv[4] = {b4.x,b4.y,b4.z,b4.w};
            if (doCvec) {
                float fbv = fb[kk];
                #pragma unroll
                for (int j = 0; j < 4; j++)
                    accC[j] = fmaf(fbv, bv[j], accC[j]);
            }
            #pragma unroll
            for (int i = 0; i < 8; i++)
                #pragma unroll
                for (int j = 0; j < 4; j++)
                    acc[i][j] = fmaf(av[i], bv[j], acc[i][j]);
        }
        __syncthreads();
    }

    int row0 = by*64 + ty*8;
    int col  = bx*64 + tx*4;
    if (doCvec && ty == 0) {
        if (bz == 0) {
            accC[0] += fcoutb[col];   accC[1] += fcoutb[col+1];
            accC[2] += fcoutb[col+2]; accC[3] += fcoutb[col+3];
        }
        *(float4*)&d_cvp[bz*DOUT + col] =
            make_float4(accC[0], accC[1], accC[2], accC[3]);
    }
    float* outp = d_S2p + (size_t)bz*1024*DOUT;
    #pragma unroll
    for (int i = 0; i < 8; i++)
        *(float4*)&outp[(row0+i)*DOUT + col] =
            make_float4(acc[i][0],acc[i][1],acc[i][2],acc[i][3]);
}

// ---------------------------------------------------------------------------
// epilogue: out[bt,m,o] = VX*A0 + VY*A1 - V*AU + base[m,o] (+cvec folded)
// Block = 384 threads, 4 bt x 16 m x 768 o.
//   warps 0-5  own columns 0..191 for bt {bt0, bt0+1}
//   warps 6-11 own columns 0..191 for bt {bt0+2, bt0+3}
// Prologue stages base tile (49 KB smem) + per-thread A regs (2 bt = 24 regs)
// + packed V scalars. Store loop: LDS + FFMA + STG only, zero global loads.
// 49 KB smem + <=56 regs -> 3 blocks/SM = 36 warps (occupancy for write stream)
// grid=(64 bt-quads, 16 m-tiles x16)
// ---------------------------------------------------------------------------
#define EPI_BT 4
#define EPI_M  16
#define EPI_THREADS 384
__global__ __launch_bounds__(EPI_THREADS, 3)
void epilogue_kernel(float* __restrict__ out) {
    extern __shared__ float4 sm[];
    float4* sBase = sm;                    // [EPI_M][192]
    float4* sVp   = sm + EPI_M*NF4;        // [EPI_M][EPI_BT] (vx, vy, v, 0)

    int bt0 = blockIdx.x * EPI_BT;
    int m0  = blockIdx.y * EPI_M;
    int t   = threadIdx.x;     // 0..383
    int w   = t >> 5, l = t & 31;
    int tcol = (w % 6)*32 + l;   // 0..191
    int bth  = w / 6;            // 0 or 1 (bt half)

    const float4* p0 = (const float4*)d_S2p;
    const float4* p1 = (const float4*)(d_S2p + (size_t)1024*DOUT);

    // cvec column = sum of KSPLIT cvp planes
    float4 cv;
    {
        const float4* cp = (const float4*)d_cvp;
        float4 c0 = cp[tcol], c1 = cp[NF4 + tcol];
        cv = make_float4(c0.x+c1.x, c0.y+c1.y, c0.z+c1.z, c0.w+c1.w);
    }
    // stage base tile: each bt-half stages 8 of the 16 rows
    #pragma unroll
    for (int k = 0; k < EPI_M/2; k++) {
        int mm = bth*(EPI_M/2) + k;
        int br = (768 + m0 + mm)*NF4 + tcol;
        float4 u = p0[br], ww = p1[br];
        sBase[mm*NF4 + tcol] = make_float4(u.x+ww.x+cv.x, u.y+ww.y+cv.y,
                                           u.z+ww.z+cv.z, u.w+ww.w+cv.w);
    }
    // A rows for this thread's column, its 2 bt, planes summed -> registers
    float4 a0[2], a1[2], au[2];
    #pragma unroll
    for (int i = 0; i < 2; i++) {
        int bt = bt0 + bth*2 + i;
        int r0 = (0*BT + bt)*NF4 + tcol;
        int r1 = (1*BT + bt)*NF4 + tcol;
        int r2 = (2*BT + bt)*NF4 + tcol;
        float4 u, ww;
        u = p0[r0]; ww = p1[r0]; a0[i] = make_float4(u.x+ww.x,u.y+ww.y,u.z+ww.z,u.w+ww.w);
        u = p0[r1]; ww = p1[r1]; a1[i] = make_float4(u.x+ww.x,u.y+ww.y,u.z+ww.z,u.w+ww.w);
        u = p0[r2]; ww = p1[r2]; au[i] = make_float4(u.x+ww.x,u.y+ww.y,u.z+ww.z,u.w+ww.w);
    }
    // V scalars packed: sVp[mm*EPI_BT+bi] = (vx, vy, v, 0)
    if (t < EPI_M*EPI_BT) {
        int mm = t >> 2, bi = t & 3;
        int src = (m0+mm)*BT + bt0 + bi;
        sVp[mm*EPI_BT + bi] = make_float4(d_VX[src], d_VY[src], d_V[src], 0.f);
    }
    __syncthreads();

    // streaming store loop: per mm, per thread: 3 LDS.128 + 24 FFMA + 2 STG.128
    #pragma unroll 4
    for (int mm = 0; mm < EPI_M; mm++) {
        float4 bv = sBase[mm*NF4 + tcol];
        int m = m0 + mm;
        #pragma unroll
        for (int i = 0; i < 2; i++) {
            float4 vp = sVp[mm*EPI_BT + bth*2 + i];
            float4 o4;
            o4.x = fmaf(vp.x, a0[i].x, fmaf(vp.y, a1[i].x, fmaf(-vp.z, au[i].x, bv.x)));
            o4.y = fmaf(vp.x, a0[i].y, fmaf(vp.y, a1[i].y, fmaf(-vp.z, au[i].y, bv.y)));
            o4.z = fmaf(vp.x, a0[i].z, fmaf(vp.y, a1[i].z, fmaf(-vp.z, au[i].z, bv.z)));
            o4.w = fmaf(vp.x, a0[i].w, fmaf(vp.y, a1[i].w, fmaf(-vp.z, au[i].w, bv.w)));
            ((float4*)out)[((bt0 + bth*2 + i)*Mm + m)*NF4 + tcol] = o4;
        }
    }
}

// ---------------------------------------------------------------------------
extern "C" void kernel_launch(void* const* d_in, const int* in_sizes, int n_in,
                              void* d_out, int out_size) {
    const float* coords = (const float*)d_in[0];
    const float* vis    = (const float*)d_in[1];
    const float* pos    = (const float*)d_in[2];
    const float* fc1w   = (const float*)d_in[3];
    const float* fc1b   = (const float*)d_in[4];
    const float* fcoutw = (const float*)d_in[5];
    const float* fcoutb = (const float*)d_in[6];
    float* out = (float*)d_out;

    static int smem_set = 0;
    int epi_smem = EPI_M*NF4*16 + EPI_M*EPI_BT*16;   // 49152 + 1024 = 50,176 B
    if (!smem_set) {
        cudaFuncSetAttribute(epilogue_kernel,
                             cudaFuncAttributeMaxDynamicSharedMemorySize, epi_smem);
        smem_set = 1;
    }

    prep_kernel    <<<Mm, 256>>>(coords, vis);
    stage1_kernel  <<<dim3(4,8,JSPLIT), 256>>>(fc1w);
    stage2_kernel  <<<dim3(12,16,KSPLIT), 128>>>(fcoutw, pos, fc1b, fcoutb);
    epilogue_kernel<<<dim3(BT/EPI_BT, Mm/EPI_M), EPI_THREADS, epi_smem>>>(out);
}

// round 9
// speedup vs baseline: 1.1354x; 1.0176x over previous
#include <cuda_runtime.h>
#include <cstdint>

#define Bb 4
#define Mm 256
#define Tt 64
#define BT 256      // B*T
#define KD 512      // 2M == D_MOT == D_ABS
#define DOUT 768
#define NF4 (DOUT/4)   // 192 float4 per row
#define JSPLIT 4
#define KSPLIT 2
#define PSZ (3*BT*KD)   // one stage1 partial plane (768 x 512)

// Scratch (no allocation allowed -> __device__ globals)
__device__ float d_V [Mm*BT];              // V [j][bt]
__device__ float d_VX[Mm*BT];
__device__ float d_VY[Mm*BT];
__device__ float d_S1p[JSPLIT*PSZ];        // stage1 partials
__device__ float d_S [PSZ];                // combined S (768 x 512)
__device__ float d_cvp[KSPLIT*DOUT];       // cvec partials (fcoutb folded into plane 0)
__device__ float d_S2p[KSPLIT*1024*DOUT];  // stage2 partials (rows 0..767 A, 768..1023 base)

__device__ __forceinline__ bool is_nan_bits(float x) {
    return (__float_as_uint(x) & 0x7fffffffu) > 0x7f800000u;
}

// ---------------------------------------------------------------------------
// prep: build V/VX/VY in (j, bt) layout.  grid=(256 j), block=256 (bt)
// ---------------------------------------------------------------------------
__global__ void prep_kernel(const float* __restrict__ coords,
                            const float* __restrict__ vis) {
    int j = blockIdx.x;
    int t = threadIdx.x;           // bt = b*64 + tt
    int b = t >> 6, tt = t & 63;
    int idx = (b*Mm + j)*Tt + tt;
    float2 xy = ((const float2*)coords)[idx];
    float v = vis[idx];
    float x = xy.x, y = xy.y;
    if (is_nan_bits(x)) { v = 0.f; x = 0.f; }
    if (is_nan_bits(y)) { y = 0.f; }
    int o = j*BT + t;
    d_V [o] = v;
    d_VX[o] = x * v;
    d_VY[o] = y * v;
}

// ---------------------------------------------------------------------------
// stage1 (software-pipelined): S0=V@We, S1=V@Wo, SU=VX@We+VY@Wo over j-slice
// grid=(4 bt-tiles x64, 8 k-tiles x64, JSPLIT), block=256
// ---------------------------------------------------------------------------
__global__ void stage1_kernel(const float* __restrict__ fc1w) {
    __shared__ float Vt [16][64], VXt[16][64], VYt[16][64];
    __shared__ float W0t[16][64], W1t[16][64];
    int bt0 = blockIdx.x * 64;
    int k0  = blockIdx.y * 64;
    int jb  = blockIdx.z * 64;
    int t  = threadIdx.x;
    int tx = t & 15;       // k quad
    int ty = t >> 4;       // bt quad
    float s0[4][4], s1[4][4], su[4][4];
    #pragma unroll
    for (int i = 0; i < 4; i++)
        #pragma unroll
        for (int j = 0; j < 4; j++) { s0[i][j]=0.f; s1[i][j]=0.f; su[i][j]=0.f; }

    int lj = t >> 4;           // load row 0..15
    int lc = (t & 15) * 4;     // load col quad

    float4 rv, rvx, rvy, rw0, rw1;
    {
        int jrow = jb + lj;
        rv  = *(const float4*)&d_V [jrow*BT + bt0 + lc];
        rvx = *(const float4*)&d_VX[jrow*BT + bt0 + lc];
        rvy = *(const float4*)&d_VY[jrow*BT + bt0 + lc];
        rw0 = *(const float4*)&fc1w[(2*jrow  )*KD + k0 + lc];
        rw1 = *(const float4*)&fc1w[(2*jrow+1)*KD + k0 + lc];
    }

    for (int jc = 0; jc < 64; jc += 16) {
        *(float4*)&Vt [lj][lc] = rv;
        *(float4*)&VXt[lj][lc] = rvx;
        *(float4*)&VYt[lj][lc] = rvy;
        *(float4*)&W0t[lj][lc] = rw0;
        *(float4*)&W1t[lj][lc] = rw1;
        __syncthreads();
        if (jc + 16 < 64) {              // prefetch next chunk (hidden by FMA)
            int jrow = jb + jc + 16 + lj;
            rv  = *(const float4*)&d_V [jrow*BT + bt0 + lc];
            rvx = *(const float4*)&d_VX[jrow*BT + bt0 + lc];
            rvy = *(const float4*)&d_VY[jrow*BT + bt0 + lc];
            rw0 = *(const float4*)&fc1w[(2*jrow  )*KD + k0 + lc];
            rw1 = *(const float4*)&fc1w[(2*jrow+1)*KD + k0 + lc];
        }
        #pragma unroll
        for (int kk = 0; kk < 16; kk++) {
            float4 v4 = *(const float4*)&Vt [kk][ty*4];
            float4 x4 = *(const float4*)&VXt[kk][ty*4];
            float4 y4 = *(const float4*)&VYt[kk][ty*4];
            float4 w0 = *(const float4*)&W0t[kk][tx*4];
            float4 w1 = *(const float4*)&W1t[kk][tx*4];
            float vv[4] = {v4.x,v4.y,v4.z,v4.w};
            float xx[4] = {x4.x,x4.y,x4.z,x4.w};
            float yy[4] = {y4.x,y4.y,y4.z,y4.w};
            float a0[4] = {w0.x,w0.y,w0.z,w0.w};
            float a1[4] = {w1.x,w1.y,w1.z,w1.w};
            #pragma unroll
            for (int i = 0; i < 4; i++)
                #pragma unroll
                for (int j = 0; j < 4; j++) {
                    s0[i][j] = fmaf(vv[i], a0[j], s0[i][j]);
                    s1[i][j] = fmaf(vv[i], a1[j], s1[i][j]);
                    su[i][j] = fmaf(xx[i], a0[j], fmaf(yy[i], a1[j], su[i][j]));
                }
        }
        __syncthreads();
    }
    float* base = d_S1p + (size_t)blockIdx.z*PSZ;
    #pragma unroll
    for (int i = 0; i < 4; i++) {
        int bt = bt0 + ty*4 + i;
        int k  = k0 + tx*4;
        *(float4*)&base[(0*BT + bt)*KD + k] = make_float4(s0[i][0],s0[i][1],s0[i][2],s0[i][3]);
        *(float4*)&base[(1*BT + bt)*KD + k] = make_float4(s1[i][0],s1[i][1],s1[i][2],s1[i][3]);
        *(float4*)&base[(2*BT + bt)*KD + k] = make_float4(su[i][0],su[i][1],su[i][2],su[i][3]);
    }
}

// combine stage1 partials: d_S = sum over JSPLIT planes (validated in R3)
__global__ void combine1_kernel() {
    int idx = blockIdx.x * 256 + threadIdx.x;   // float4 index, 98304 total
    const float4* p = (const float4*)d_S1p;
    const int plane = PSZ/4;
    float4 a = p[idx], b = p[plane + idx], c = p[2*plane + idx], d = p[3*plane + idx];
    float4 r;
    r.x = (a.x+b.x)+(c.x+d.x); r.y = (a.y+b.y)+(c.y+d.y);
    r.z = (a.z+b.z)+(c.z+d.z); r.w = (a.w+b.w)+(c.w+d.w);
    ((float4*)d_S)[idx] = r;
}

// ---------------------------------------------------------------------------
// stage2 (pipelined, fused cvec): C (1024 x 768), K = 512, split-K = 2
//   rows    0..767 : A = d_S, B = W2_top
//   rows 768..1023 : A = pos, B = W2_bot
// by==0 blocks also accumulate cvec = fc1b @ W2_top -> d_cvp (+fcoutb, bz=0)
// grid=(12 n x64, 16 m x64, 2 ksplit), block=128, microtile 8x4
// ---------------------------------------------------------------------------
__global__ void stage2_kernel(const float* __restrict__ fcoutw,
                              const float* __restrict__ pos,
                              const float* __restrict__ fc1b,
                              const float* __restrict__ fcoutb) {
    __shared__ float At[16][64];
    __shared__ float Bt[16][64];
    __shared__ float fb[16];
    int bx = blockIdx.x;           // n tile
    int by = blockIdx.y;           // m tile
    int bz = blockIdx.z;           // k split
    bool isBase = (by >= 12);
    bool doCvec = (by == 0);       // stages W2_top -> correct weights for cvec
    const float* Ap = isBase ? (pos + (by-12)*64*KD) : (d_S + by*64*KD);
    const float* Bp = fcoutw + (isBase ? KD*DOUT : 0) + bx*64;
    int t  = threadIdx.x;
    int tx = t & 15;    // 4 cols
    int ty = t >> 4;    // 8 rows
    float acc[8][4];
    #pragma unroll
    for (int i = 0; i < 8; i++)
        #pragma unroll
        for (int j = 0; j < 4; j++) acc[i][j] = 0.f;
    float accC[4] = {0.f, 0.f, 0.f, 0.f};

    int arow = t >> 1;          // 0..63
    int koff = (t & 1) * 8;
    int bk   = t >> 4;          // 0..7 (and +8)
    int bn   = (t & 15) * 4;

    int kbeg = bz*256, kend = kbeg + 256;
    float4 ra0, ra1, rb0, rb1;
    ra0 = *(const float4*)&Ap[arow*KD + kbeg + koff];
    ra1 = *(const float4*)&Ap[arow*KD + kbeg + koff + 4];
    rb0 = *(const float4*)&Bp[(kbeg+bk  )*DOUT + bn];
    rb1 = *(const float4*)&Bp[(kbeg+bk+8)*DOUT + bn];

    for (int kc = kbeg; kc < kend; kc += 16) {
        At[koff+0][arow] = ra0.x; At[koff+1][arow] = ra0.y;
        At[koff+2][arow] = ra0.z; At[koff+3][arow] = ra0.w;
        At[koff+4][arow] = ra1.x; At[koff+5][arow] = ra1.y;
        At[koff+6][arow] = ra1.z; At[koff+7][arow] = ra1.w;
        *(float4*)&Bt[bk  ][bn] = rb0;
        *(float4*)&Bt[bk+8][bn] = rb1;
        if (doCvec && t < 16) fb[t] = fc1b[kc + t];
        __syncthreads();
        if (kc + 16 < kend) {            // prefetch next chunk
            ra0 = *(const float4*)&Ap[arow*KD + kc + 16 + koff];
            ra1 = *(const float4*)&Ap[arow*KD + kc + 16 + koff + 4];
            rb0 = *(const float4*)&Bp[(kc+16+bk  )*DOUT + bn];
            rb1 = *(const float4*)&Bp[(kc+16+bk+8)*DOUT + bn];
        }
        #pragma unroll
        for (int kk = 0; kk < 16; kk++) {
            float4 b4 = *(const float4*)&Bt[kk][tx*4];
            float4 aA = *(const float4*)&At[kk][ty*8];
            float4 aB = *(const float4*)&At[kk][ty*8 + 4];
            float av[8] = {aA.x,aA.y,aA.z,aA.w,aB.x,aB.y,aB.z,aB.w};
            float bv[4] = {b4.x,b4.y,b4.z,b4.w};
            if (doCvec) {
                float fbv = fb[kk];
                #pragma unroll
                for (int j = 0; j < 4; j++)
                    accC[j] = fmaf(fbv, bv[j], accC[j]);
            }
            #pragma unroll
            for (int i = 0; i < 8; i++)
                #pragma unroll
                for (int j = 0; j < 4; j++)
                    acc[i][j] = fmaf(av[i], bv[j], acc[i][j]);
        }
        __syncthreads();
    }

    int row0 = by*64 + ty*8;
    int col  = bx*64 + tx*4;
    if (doCvec && ty == 0) {
        if (bz == 0) {
            accC[0] += fcoutb[col];   accC[1] += fcoutb[col+1];
            accC[2] += fcoutb[col+2]; accC[3] += fcoutb[col+3];
        }
        *(float4*)&d_cvp[bz*DOUT + col] =
            make_float4(accC[0], accC[1], accC[2], accC[3]);
    }
    float* outp = d_S2p + (size_t)bz*1024*DOUT;
    #pragma unroll
    for (int i = 0; i < 8; i++)
        *(float4*)&outp[(row0+i)*DOUT + col] =
            make_float4(acc[i][0],acc[i][1],acc[i][2],acc[i][3]);
}

// ---------------------------------------------------------------------------
// epilogue: out[bt,m,o] = VX*A0 + VY*A1 - V*AU + base[m,o] (+cvec folded)
// 384 threads: warps 0-5 -> bt {0,1}, warps 6-11 -> bt {2,3} of the quad.
// Base tile (16 m rows, planes+cvec summed) in 49 KB smem; A rows in regs.
// Store loop: LDS + FFMA + STG only.  grid=(64 bt-quads, 16 m-tiles)
// ---------------------------------------------------------------------------
#define EPI_BT 4
#define EPI_M  16
#define EPI_THREADS 384
__global__ __launch_bounds__(EPI_THREADS, 3)
void epilogue_kernel(float* __restrict__ out) {
    extern __shared__ float4 sm[];
    float4* sBase = sm;                    // [EPI_M][192]
    float4* sVp   = sm + EPI_M*NF4;        // [EPI_M][EPI_BT] (vx, vy, v, 0)

    int bt0 = blockIdx.x * EPI_BT;
    int m0  = blockIdx.y * EPI_M;
    int t   = threadIdx.x;     // 0..383
    int w   = t >> 5, l = t & 31;
    int tcol = (w % 6)*32 + l;   // 0..191
    int bth  = w / 6;            // 0 or 1 (bt half)

    const float4* p0 = (const float4*)d_S2p;
    const float4* p1 = (const float4*)(d_S2p + (size_t)1024*DOUT);

    float4 cv;
    {
        const float4* cp = (const float4*)d_cvp;
        float4 c0 = cp[tcol], c1 = cp[NF4 + tcol];
        cv = make_float4(c0.x+c1.x, c0.y+c1.y, c0.z+c1.z, c0.w+c1.w);
    }
    #pragma unroll
    for (int k = 0; k < EPI_M/2; k++) {
        int mm = bth*(EPI_M/2) + k;
        int br = (768 + m0 + mm)*NF4 + tcol;
        float4 u = p0[br], ww = p1[br];
        sBase[mm*NF4 + tcol] = make_float4(u.x+ww.x+cv.x, u.y+ww.y+cv.y,
                                           u.z+ww.z+cv.z, u.w+ww.w+cv.w);
    }
    float4 a0[2], a1[2], au[2];
    #pragma unroll
    for (int i = 0; i < 2; i++) {
        int bt = bt0 + bth*2 + i;
        int r0 = (0*BT + bt)*NF4 + tcol;
        int r1 = (1*BT + bt)*NF4 + tcol;
        int r2 = (2*BT + bt)*NF4 + tcol;
        float4 u, ww;
        u = p0[r0]; ww = p1[r0]; a0[i] = make_float4(u.x+ww.x,u.y+ww.y,u.z+ww.z,u.w+ww.w);
        u = p0[r1]; ww = p1[r1]; a1[i] = make_float4(u.x+ww.x,u.y+ww.y,u.z+ww.z,u.w+ww.w);
        u = p0[r2]; ww = p1[r2]; au[i] = make_float4(u.x+ww.x,u.y+ww.y,u.z+ww.z,u.w+ww.w);
    }
    if (t < EPI_M*EPI_BT) {
        int mm = t >> 2, bi = t & 3;
        int src = (m0+mm)*BT + bt0 + bi;
        sVp[mm*EPI_BT + bi] = make_float4(d_VX[src], d_VY[src], d_V[src], 0.f);
    }
    __syncthreads();

    #pragma unroll 4
    for (int mm = 0; mm < EPI_M; mm++) {
        float4 bv = sBase[mm*NF4 + tcol];
        int m = m0 + mm;
        #pragma unroll
        for (int i = 0; i < 2; i++) {
            float4 vp = sVp[mm*EPI_BT + bth*2 + i];
            float4 o4;
            o4.x = fmaf(vp.x, a0[i].x, fmaf(vp.y, a1[i].x, fmaf(-vp.z, au[i].x, bv.x)));
            o4.y = fmaf(vp.x, a0[i].y, fmaf(vp.y, a1[i].y, fmaf(-vp.z, au[i].y, bv.y)));
            o4.z = fmaf(vp.x, a0[i].z, fmaf(vp.y, a1[i].z, fmaf(-vp.z, au[i].z, bv.z)));
            o4.w = fmaf(vp.x, a0[i].w, fmaf(vp.y, a1[i].w, fmaf(-vp.z, au[i].w, bv.w)));
            ((float4*)out)[((bt0 + bth*2 + i)*Mm + m)*NF4 + tcol] = o4;
        }
    }
}

// ---------------------------------------------------------------------------
extern "C" void kernel_launch(void* const* d_in, const int* in_sizes, int n_in,
                              void* d_out, int out_size) {
    const float* coords = (const float*)d_in[0];
    const float* vis    = (const float*)d_in[1];
    const float* pos    = (const float*)d_in[2];
    const float* fc1w   = (const float*)d_in[3];
    const float* fc1b   = (const float*)d_in[4];
    const float* fcoutw = (const float*)d_in[5];
    const float* fcoutb = (const float*)d_in[6];
    float* out = (float*)d_out;

    static int smem_set = 0;
    int epi_smem = EPI_M*NF4*16 + EPI_M*EPI_BT*16;   // 50,176 B
    if (!smem_set) {
        cudaFuncSetAttribute(epilogue_kernel,
                             cudaFuncAttributeMaxDynamicSharedMemorySize, epi_smem);
        smem_set = 1;
    }

    prep_kernel    <<<Mm, 256>>>(coords, vis);
    stage1_kernel  <<<dim3(4,8,JSPLIT), 256>>>(fc1w);
    combine1_kernel<<<384, 256>>>();
    stage2_kernel  <<<dim3(12,16,KSPLIT), 128>>>(fcoutw, pos, fc1b, fcoutb);
    epilogue_kernel<<<dim3(BT/EPI_BT, Mm/EPI_M), EPI_THREADS, epi_smem>>>(out);
}

// round 10
// speedup vs baseline: 1.1611x; 1.0226x over previous
#include <cuda_runtime.h>
#include <cstdint>

#define Bb 4
#define Mm 256
#define Tt 64
#define BT 256      // B*T
#define KD 512      // 2M == D_MOT == D_ABS
#define DOUT 768
#define NF4 (DOUT/4)   // 192 float4 per row
#define JSPLIT 4
#define KSPLIT 4       // A-rows split; base rows use only planes 0,1 (256 k each)
#define PSZ (3*BT*KD)  // one stage1 partial plane (768 x 512)

// Scratch (no allocation allowed -> __device__ globals)
__device__ float d_V [Mm*BT];               // V [j][bt]
__device__ float d_VX[Mm*BT];
__device__ float d_VY[Mm*BT];
__device__ float d_S1p[JSPLIT*PSZ];         // stage1 partials
__device__ float d_S [PSZ];                 // combined S (768 x 512)
__device__ float d_cvp[KSPLIT*DOUT];        // cvec partials (fcoutb folded into plane 0)
__device__ float d_S2p[KSPLIT*1024*DOUT];   // stage2 partials

__device__ __forceinline__ bool is_nan_bits(float x) {
    return (__float_as_uint(x) & 0x7fffffffu) > 0x7f800000u;
}

// ---------------------------------------------------------------------------
// prep: build V/VX/VY in (j, bt) layout.  grid=(256 j), block=256 (bt)
// ---------------------------------------------------------------------------
__global__ void prep_kernel(const float* __restrict__ coords,
                            const float* __restrict__ vis) {
    int j = blockIdx.x;
    int t = threadIdx.x;           // bt = b*64 + tt
    int b = t >> 6, tt = t & 63;
    int idx = (b*Mm + j)*Tt + tt;
    float2 xy = ((const float2*)coords)[idx];
    float v = vis[idx];
    float x = xy.x, y = xy.y;
    if (is_nan_bits(x)) { v = 0.f; x = 0.f; }
    if (is_nan_bits(y)) { y = 0.f; }
    int o = j*BT + t;
    d_V [o] = v;
    d_VX[o] = x * v;
    d_VY[o] = y * v;
}

// ---------------------------------------------------------------------------
// stage1 (software-pipelined): S0=V@We, S1=V@Wo, SU=VX@We+VY@Wo over j-slice
// grid=(4 bt-tiles x64, 8 k-tiles x64, JSPLIT), block=256
// ---------------------------------------------------------------------------
__global__ void stage1_kernel(const float* __restrict__ fc1w) {
    __shared__ float Vt [16][64], VXt[16][64], VYt[16][64];
    __shared__ float W0t[16][64], W1t[16][64];
    int bt0 = blockIdx.x * 64;
    int k0  = blockIdx.y * 64;
    int jb  = blockIdx.z * 64;
    int t  = threadIdx.x;
    int tx = t & 15;       // k quad
    int ty = t >> 4;       // bt quad
    float s0[4][4], s1[4][4], su[4][4];
    #pragma unroll
    for (int i = 0; i < 4; i++)
        #pragma unroll
        for (int j = 0; j < 4; j++) { s0[i][j]=0.f; s1[i][j]=0.f; su[i][j]=0.f; }

    int lj = t >> 4;           // load row 0..15
    int lc = (t & 15) * 4;     // load col quad

    float4 rv, rvx, rvy, rw0, rw1;
    {
        int jrow = jb + lj;
        rv  = *(const float4*)&d_V [jrow*BT + bt0 + lc];
        rvx = *(const float4*)&d_VX[jrow*BT + bt0 + lc];
        rvy = *(const float4*)&d_VY[jrow*BT + bt0 + lc];
        rw0 = *(const float4*)&fc1w[(2*jrow  )*KD + k0 + lc];
        rw1 = *(const float4*)&fc1w[(2*jrow+1)*KD + k0 + lc];
    }

    for (int jc = 0; jc < 64; jc += 16) {
        *(float4*)&Vt [lj][lc] = rv;
        *(float4*)&VXt[lj][lc] = rvx;
        *(float4*)&VYt[lj][lc] = rvy;
        *(float4*)&W0t[lj][lc] = rw0;
        *(float4*)&W1t[lj][lc] = rw1;
        __syncthreads();
        if (jc + 16 < 64) {              // prefetch next chunk (hidden by FMA)
            int jrow = jb + jc + 16 + lj;
            rv  = *(const float4*)&d_V [jrow*BT + bt0 + lc];
            rvx = *(const float4*)&d_VX[jrow*BT + bt0 + lc];
            rvy = *(const float4*)&d_VY[jrow*BT + bt0 + lc];
            rw0 = *(const float4*)&fc1w[(2*jrow  )*KD + k0 + lc];
            rw1 = *(const float4*)&fc1w[(2*jrow+1)*KD + k0 + lc];
        }
        #pragma unroll
        for (int kk = 0; kk < 16; kk++) {
            float4 v4 = *(const float4*)&Vt [kk][ty*4];
            float4 x4 = *(const float4*)&VXt[kk][ty*4];
            float4 y4 = *(const float4*)&VYt[kk][ty*4];
            float4 w0 = *(const float4*)&W0t[kk][tx*4];
            float4 w1 = *(const float4*)&W1t[kk][tx*4];
            float vv[4] = {v4.x,v4.y,v4.z,v4.w};
            float xx[4] = {x4.x,x4.y,x4.z,x4.w};
            float yy[4] = {y4.x,y4.y,y4.z,y4.w};
            float a0[4] = {w0.x,w0.y,w0.z,w0.w};
            float a1[4] = {w1.x,w1.y,w1.z,w1.w};
            #pragma unroll
            for (int i = 0; i < 4; i++)
                #pragma unroll
                for (int j = 0; j < 4; j++) {
                    s0[i][j] = fmaf(vv[i], a0[j], s0[i][j]);
                    s1[i][j] = fmaf(vv[i], a1[j], s1[i][j]);
                    su[i][j] = fmaf(xx[i], a0[j], fmaf(yy[i], a1[j], su[i][j]));
                }
        }
        __syncthreads();
    }
    float* base = d_S1p + (size_t)blockIdx.z*PSZ;
    #pragma unroll
    for (int i = 0; i < 4; i++) {
        int bt = bt0 + ty*4 + i;
        int k  = k0 + tx*4;
        *(float4*)&base[(0*BT + bt)*KD + k] = make_float4(s0[i][0],s0[i][1],s0[i][2],s0[i][3]);
        *(float4*)&base[(1*BT + bt)*KD + k] = make_float4(s1[i][0],s1[i][1],s1[i][2],s1[i][3]);
        *(float4*)&base[(2*BT + bt)*KD + k] = make_float4(su[i][0],su[i][1],su[i][2],su[i][3]);
    }
}

// combine stage1 partials: d_S = sum over JSPLIT planes
__global__ void combine1_kernel() {
    int idx = blockIdx.x * 256 + threadIdx.x;   // float4 index, 98304 total
    const float4* p = (const float4*)d_S1p;
    const int plane = PSZ/4;
    float4 a = p[idx], b = p[plane + idx], c = p[2*plane + idx], d = p[3*plane + idx];
    float4 r;
    r.x = (a.x+b.x)+(c.x+d.x); r.y = (a.y+b.y)+(c.y+d.y);
    r.z = (a.z+b.z)+(c.z+d.z); r.w = (a.w+b.w)+(c.w+d.w);
    ((float4*)d_S)[idx] = r;
}

// ---------------------------------------------------------------------------
// stage2: C (1024 x 768), K = 512.
//   A rows   (by 0..11, rows 0..767):   A = d_S, B = W2_top, split-K=4 (128 k/plane)
//   base rows(by 12..15, rows 768..1023): A = pos, B = W2_bot, split-K=2 (256 k, bz<2)
// by==0 blocks accumulate cvec = fc1b @ W2_top slice -> d_cvp[bz] (4 planes).
// grid=(12, 16, 4), block=128, microtile 8x4, reg-prefetch pipeline.
// ---------------------------------------------------------------------------
__global__ void stage2_kernel(const float* __restrict__ fcoutw,
                              const float* __restrict__ pos,
                              const float* __restrict__ fc1b,
                              const float* __restrict__ fcoutb) {
    __shared__ float At[16][64];
    __shared__ float Bt[16][64];
    __shared__ float fb[16];
    int bx = blockIdx.x;           // n tile
    int by = blockIdx.y;           // m tile
    int bz = blockIdx.z;           // k split
    bool isBase = (by >= 12);
    if (isBase && bz >= 2) return;            // base rows only in planes 0,1
    bool doCvec = (by == 0);
    const float* Ap = isBase ? (pos + (by-12)*64*KD) : (d_S + by*64*KD);
    const float* Bp = fcoutw + (isBase ? KD*DOUT : 0) + bx*64;
    int t  = threadIdx.x;
    int tx = t & 15;    // 4 cols
    int ty = t >> 4;    // 8 rows
    float acc[8][4];
    #pragma unroll
    for (int i = 0; i < 8; i++)
        #pragma unroll
        for (int j = 0; j < 4; j++) acc[i][j] = 0.f;
    float accC[4] = {0.f, 0.f, 0.f, 0.f};

    int arow = t >> 1;          // 0..63
    int koff = (t & 1) * 8;
    int bk   = t >> 4;          // 0..7 (and +8)
    int bn   = (t & 15) * 4;

    int kbeg = isBase ? bz*256 : bz*128;
    int kend = kbeg + (isBase ? 256 : 128);
    float4 ra0, ra1, rb0, rb1;
    ra0 = *(const float4*)&Ap[arow*KD + kbeg + koff];
    ra1 = *(const float4*)&Ap[arow*KD + kbeg + koff + 4];
    rb0 = *(const float4*)&Bp[(kbeg+bk  )*DOUT + bn];
    rb1 = *(const float4*)&Bp[(kbeg+bk+8)*DOUT + bn];

    for (int kc = kbeg; kc < kend; kc += 16) {
        At[koff+0][arow] = ra0.x; At[koff+1][arow] = ra0.y;
        At[koff+2][arow] = ra0.z; At[koff+3][arow] = ra0.w;
        At[koff+4][arow] = ra1.x; At[koff+5][arow] = ra1.y;
        At[koff+6][arow] = ra1.z; At[koff+7][arow] = ra1.w;
        *(float4*)&Bt[bk  ][bn] = rb0;
        *(float4*)&Bt[bk+8][bn] = rb1;
        if (doCvec && t < 16) fb[t] = fc1b[kc + t];
        __syncthreads();
        if (kc + 16 < kend) {            // prefetch next chunk
            ra0 = *(const float4*)&Ap[arow*KD + kc + 16 + koff];
            ra1 = *(const float4*)&Ap[arow*KD + kc + 16 + koff + 4];
            rb0 = *(const float4*)&Bp[(kc+16+bk  )*DOUT + bn];
            rb1 = *(const float4*)&Bp[(kc+16+bk+8)*DOUT + bn];
        }
        #pragma unroll
        for (int kk = 0; kk < 16; kk++) {
            float4 b4 = *(const float4*)&Bt[kk][tx*4];
            float4 aA = *(const float4*)&At[kk][ty*8];
            float4 aB = *(const float4*)&At[kk][ty*8 + 4];
            float av[8] = {aA.x,aA.y,aA.z,aA.w,aB.x,aB.y,aB.z,aB.w};
            float bv[4] = {b4.x,b4.y,b4.z,b4.w};
            if (doCvec) {
                float fbv = fb[kk];
                #pragma unroll
                for (int j = 0; j < 4; j++)
                    accC[j] = fmaf(fbv, bv[j], accC[j]);
            }
            #pragma unroll
            for (int i = 0; i < 8; i++)
                #pragma unroll
                for (int j = 0; j < 4; j++)
                    acc[i][j] = fmaf(av[i], bv[j], acc[i][j]);
        }
        __syncthreads();
    }

    int row0 = by*64 + ty*8;
    int col  = bx*64 + tx*4;
    if (doCvec && ty == 0) {
        if (bz == 0) {
            accC[0] += fcoutb[col];   accC[1] += fcoutb[col+1];
            accC[2] += fcoutb[col+2]; accC[3] += fcoutb[col+3];
        }
        *(float4*)&d_cvp[bz*DOUT + col] =
            make_float4(accC[0], accC[1], accC[2], accC[3]);
    }
    float* outp = d_S2p + (size_t)bz*1024*DOUT;
    #pragma unroll
    for (int i = 0; i < 8; i++)
        *(float4*)&outp[(row0+i)*DOUT + col] =
            make_float4(acc[i][0],acc[i][1],acc[i][2],acc[i][3]);
}

// ---------------------------------------------------------------------------
// epilogue: out[bt,m,o] = VX*A0 + VY*A1 - V*AU + base[m,o] (+cvec folded)
// A rows = sum of 4 planes; base rows = sum of planes 0,1; cvec = 4 cvp planes.
// 384 threads: warps 0-5 -> bt {0,1}, warps 6-11 -> bt {2,3}. EPI_M=32 rows
// of base in 98 KB smem (2 blocks/SM = 24 warps). Store loop: LDS+FFMA+STG.
// grid=(64 bt-quads, 8 m-tiles x32)
// ---------------------------------------------------------------------------
#define EPI_BT 4
#define EPI_M  32
#define EPI_THREADS 384
__global__ __launch_bounds__(EPI_THREADS, 2)
void epilogue_kernel(float* __restrict__ out) {
    extern __shared__ float4 sm[];
    float4* sBase = sm;                    // [EPI_M][192]
    float4* sVp   = sm + EPI_M*NF4;        // [EPI_M][EPI_BT] (vx, vy, v, 0)

    int bt0 = blockIdx.x * EPI_BT;
    int m0  = blockIdx.y * EPI_M;
    int t   = threadIdx.x;     // 0..383
    int w   = t >> 5, l = t & 31;
    int tcol = (w % 6)*32 + l;   // 0..191
    int bth  = w / 6;            // 0 or 1 (bt half)

    const int PL = 1024*NF4;     // one S2 plane in float4
    const float4* p0 = (const float4*)d_S2p;
    const float4* p1 = p0 + PL;
    const float4* p2 = p0 + 2*PL;
    const float4* p3 = p0 + 3*PL;

    float4 cv;
    {
        const float4* cp = (const float4*)d_cvp;
        float4 c0 = cp[tcol], c1 = cp[NF4+tcol], c2 = cp[2*NF4+tcol], c3 = cp[3*NF4+tcol];
        cv = make_float4((c0.x+c1.x)+(c2.x+c3.x), (c0.y+c1.y)+(c2.y+c3.y),
                         (c0.z+c1.z)+(c2.z+c3.z), (c0.w+c1.w)+(c2.w+c3.w));
    }
    // stage base tile: planes 0,1 + cvec; each bt-half stages 16 of 32 rows
    #pragma unroll 4
    for (int k = 0; k < EPI_M/2; k++) {
        int mm = bth*(EPI_M/2) + k;
        int br = (768 + m0 + mm)*NF4 + tcol;
        float4 u = p0[br], ww = p1[br];
        sBase[mm*NF4 + tcol] = make_float4(u.x+ww.x+cv.x, u.y+ww.y+cv.y,
                                           u.z+ww.z+cv.z, u.w+ww.w+cv.w);
    }
    // A rows: sum of 4 planes -> registers (2 bt per thread)
    float4 a0[2], a1[2], au[2];
    #pragma unroll
    for (int i = 0; i < 2; i++) {
        int bt = bt0 + bth*2 + i;
        #pragma unroll
        for (int r = 0; r < 3; r++) {
            int ri = (r*BT + bt)*NF4 + tcol;
            float4 u = p0[ri], ww = p1[ri], y = p2[ri], z = p3[ri];
            float4 s = make_float4((u.x+ww.x)+(y.x+z.x), (u.y+ww.y)+(y.y+z.y),
                                   (u.z+ww.z)+(y.z+z.z), (u.w+ww.w)+(y.w+z.w));
            if (r == 0) a0[i] = s; else if (r == 1) a1[i] = s; else au[i] = s;
        }
    }
    if (t < EPI_M*EPI_BT) {
        int mm = t >> 2, bi = t & 3;
        int src = (m0+mm)*BT + bt0 + bi;
        sVp[mm*EPI_BT + bi] = make_float4(d_VX[src], d_VY[src], d_V[src], 0.f);
    }
    __syncthreads();

    #pragma unroll 4
    for (int mm = 0; mm < EPI_M; mm++) {
        float4 bv = sBase[mm*NF4 + tcol];
        int m = m0 + mm;
        #pragma unroll
        for (int i = 0; i < 2; i++) {
            float4 vp = sVp[mm*EPI_BT + bth*2 + i];
            float4 o4;
            o4.x = fmaf(vp.x, a0[i].x, fmaf(vp.y, a1[i].x, fmaf(-vp.z, au[i].x, bv.x)));
            o4.y = fmaf(vp.x, a0[i].y, fmaf(vp.y, a1[i].y, fmaf(-vp.z, au[i].y, bv.y)));
            o4.z = fmaf(vp.x, a0[i].z, fmaf(vp.y, a1[i].z, fmaf(-vp.z, au[i].z, bv.z)));
            o4.w = fmaf(vp.x, a0[i].w, fmaf(vp.y, a1[i].w, fmaf(-vp.z, au[i].w, bv.w)));
            ((float4*)out)[((bt0 + bth*2 + i)*Mm + m)*NF4 + tcol] = o4;
        }
    }
}

// ---------------------------------------------------------------------------
extern "C" void kernel_launch(void* const* d_in, const int* in_sizes, int n_in,
                              void* d_out, int out_size) {
    const float* coords = (const float*)d_in[0];
    const float* vis    = (const float*)d_in[1];
    const float* pos    = (const float*)d_in[2];
    const float* fc1w   = (const float*)d_in[3];
    const float* fc1b   = (const float*)d_in[4];
    const float* fcoutw = (const float*)d_in[5];
    const float* fcoutb = (const float*)d_in[6];
    float* out = (float*)d_out;

    static int smem_set = 0;
    int epi_smem = EPI_M*NF4*16 + EPI_M*EPI_BT*16;   // 98304 + 2048 = 100,352 B
    if (!smem_set) {
        cudaFuncSetAttribute(epilogue_kernel,
                             cudaFuncAttributeMaxDynamicSharedMemorySize, epi_smem);
        smem_set = 1;
    }

    prep_kernel    <<<Mm, 256>>>(coords, vis);
    stage1_kernel  <<<dim3(4,8,JSPLIT), 256>>>(fc1w);
    combine1_kernel<<<384, 256>>>();
    stage2_kernel  <<<dim3(12,16,KSPLIT), 128>>>(fcoutw, pos, fc1b, fcoutb);
    epilogue_kernel<<<dim3(BT/EPI_BT, Mm/EPI_M), EPI_THREADS, epi_smem>>>(out);
}

// round 11
// speedup vs baseline: 1.2517x; 1.0781x over previous
#include <cuda_runtime.h>
#include <cstdint>

#define Bb 4
#define Mm 256
#define Tt 64
#define BT 256      // B*T
#define KD 512      // 2M == D_MOT == D_ABS
#define DOUT 768
#define NF4 (DOUT/4)   // 192 float4 per row
#define JSPLIT 4
#define KSPLIT 8       // stage2 A-row k-split (64 k per plane); base rows use 2 (256 k)
#define PSZ (3*BT*KD)  // S buffer (768 x 512)

// One accumulation arena, zero-filled each launch, RED.ADD accumulated.
//   [0, PSZ)                    : S  (S0/S1/SU rows, 768 x 512)
//   [PSZ, PSZ+1024*DOUT)        : S2 (rows 0..767 = A0/A1/AU ; 768..1023 = base)
//   [PSZ+1024*DOUT, +DOUT)      : cvec (fc1b@W2_top + fc_out_b)
#define OFF_S  0
#define OFF_S2 (PSZ)
#define OFF_CV (PSZ + 1024*DOUT)
#define TOTF   (PSZ + 1024*DOUT + DOUT)
__device__ float d_acc[TOTF];

__device__ __forceinline__ bool is_nan_bits(float x) {
    return (__float_as_uint(x) & 0x7fffffffu) > 0x7f800000u;
}

// ---------------------------------------------------------------------------
// zero the accumulation arena (295104 float4)
// ---------------------------------------------------------------------------
__global__ void zero_kernel() {
    int idx = blockIdx.x * 256 + threadIdx.x;
    if (idx < TOTF/4)
        ((float4*)d_acc)[idx] = make_float4(0.f, 0.f, 0.f, 0.f);
}

// ---------------------------------------------------------------------------
// stage1 (inline V from coords, RED.ADD output): over j-slice,
//   S0 += V@We, S1 += V@Wo, SU += VX@We + VY@Wo
// grid=(4 bt-tiles x64, 8 k-tiles x64, JSPLIT), block=256.
// Each bt-tile is exactly one batch b = blockIdx.x.
// ---------------------------------------------------------------------------
__global__ void stage1_kernel(const float* __restrict__ coords,
                              const float* __restrict__ vis,
                              const float* __restrict__ fc1w) {
    __shared__ float Vt [16][64], VXt[16][64], VYt[16][64];
    __shared__ float W0t[16][64], W1t[16][64];
    int b   = blockIdx.x;          // batch == bt-tile
    int bt0 = b * 64;
    int k0  = blockIdx.y * 64;
    int jb  = blockIdx.z * 64;
    int t  = threadIdx.x;
    int tx = t & 15;       // k quad
    int ty = t >> 4;       // bt quad
    float s0[4][4], s1[4][4], su[4][4];
    #pragma unroll
    for (int i = 0; i < 4; i++)
        #pragma unroll
        for (int j = 0; j < 4; j++) { s0[i][j]=0.f; s1[i][j]=0.f; su[i][j]=0.f; }

    int lj = t >> 4;           // load row 0..15
    int lc = (t & 15) * 4;     // load col quad (tt within batch)

    float4 c01, c23, vv4, rw0, rw1;
    {
        int jrow = jb + lj;
        int cbase = (b*Mm + jrow)*Tt + lc;
        c01 = *(const float4*)&coords[2*cbase];
        c23 = *(const float4*)&coords[2*cbase + 4];
        vv4 = *(const float4*)&vis[cbase];
        rw0 = *(const float4*)&fc1w[(2*jrow  )*KD + k0 + lc];
        rw1 = *(const float4*)&fc1w[(2*jrow+1)*KD + k0 + lc];
    }

    for (int jc = 0; jc < 64; jc += 16) {
        {   // convert + store to smem (vectorized)
            float xs[4] = {c01.x, c01.z, c23.x, c23.z};
            float ys[4] = {c01.y, c01.w, c23.y, c23.w};
            float vs[4] = {vv4.x, vv4.y, vv4.z, vv4.w};
            #pragma unroll
            for (int e = 0; e < 4; e++) {
                if (is_nan_bits(xs[e])) { vs[e] = 0.f; xs[e] = 0.f; }
                if (is_nan_bits(ys[e])) { ys[e] = 0.f; }
            }
            *(float4*)&Vt [lj][lc] = make_float4(vs[0], vs[1], vs[2], vs[3]);
            *(float4*)&VXt[lj][lc] = make_float4(xs[0]*vs[0], xs[1]*vs[1], xs[2]*vs[2], xs[3]*vs[3]);
            *(float4*)&VYt[lj][lc] = make_float4(ys[0]*vs[0], ys[1]*vs[1], ys[2]*vs[2], ys[3]*vs[3]);
            *(float4*)&W0t[lj][lc] = rw0;
            *(float4*)&W1t[lj][lc] = rw1;
        }
        __syncthreads();
        if (jc + 16 < 64) {            // prefetch next chunk (hidden by FMA)
            int jrow = jb + jc + 16 + lj;
            int cbase = (b*Mm + jrow)*Tt + lc;
            c01 = *(const float4*)&coords[2*cbase];
            c23 = *(const float4*)&coords[2*cbase + 4];
            vv4 = *(const float4*)&vis[cbase];
            rw0 = *(const float4*)&fc1w[(2*jrow  )*KD + k0 + lc];
            rw1 = *(const float4*)&fc1w[(2*jrow+1)*KD + k0 + lc];
        }
        #pragma unroll
        for (int kk = 0; kk < 16; kk++) {
            float4 v4 = *(const float4*)&Vt [kk][ty*4];
            float4 x4 = *(const float4*)&VXt[kk][ty*4];
            float4 y4 = *(const float4*)&VYt[kk][ty*4];
            float4 w0 = *(const float4*)&W0t[kk][tx*4];
            float4 w1 = *(const float4*)&W1t[kk][tx*4];
            float vv[4] = {v4.x,v4.y,v4.z,v4.w};
            float xx[4] = {x4.x,x4.y,x4.z,x4.w};
            float yy[4] = {y4.x,y4.y,y4.z,y4.w};
            float a0[4] = {w0.x,w0.y,w0.z,w0.w};
            float a1[4] = {w1.x,w1.y,w1.z,w1.w};
            #pragma unroll
            for (int i = 0; i < 4; i++)
                #pragma unroll
                for (int j = 0; j < 4; j++) {
                    s0[i][j] = fmaf(vv[i], a0[j], s0[i][j]);
                    s1[i][j] = fmaf(vv[i], a1[j], s1[i][j]);
                    su[i][j] = fmaf(xx[i], a0[j], fmaf(yy[i], a1[j], su[i][j]));
                }
        }
        __syncthreads();
    }
    // RED.ADD into the single S plane
    float* S = d_acc + OFF_S;
    #pragma unroll
    for (int i = 0; i < 4; i++) {
        int bt = bt0 + ty*4 + i;
        int k  = k0 + tx*4;
        #pragma unroll
        for (int j = 0; j < 4; j++) {
            atomicAdd(&S[(0*BT + bt)*KD + k + j], s0[i][j]);
            atomicAdd(&S[(1*BT + bt)*KD + k + j], s1[i][j]);
            atomicAdd(&S[(2*BT + bt)*KD + k + j], su[i][j]);
        }
    }
}

// ---------------------------------------------------------------------------
// stage2 (RED.ADD output, fused cvec): C (1024 x 768), K = 512.
//   A rows   (by 0..11):  A = S,   B = W2_top, split-K=8 (64 k/plane)
//   base rows(by 12..15): A = pos, B = W2_bot, split-K=2 (256 k, bz<2)
// by==0 blocks accumulate cvec = fc1b @ W2_top slice into d_acc cvec.
// grid=(12, 16, 8), block=128, microtile 8x4, reg-prefetch pipeline.
// ---------------------------------------------------------------------------
__global__ void stage2_kernel(const float* __restrict__ fcoutw,
                              const float* __restrict__ pos,
                              const float* __restrict__ fc1b,
                              const float* __restrict__ fcoutb) {
    __shared__ float At[16][64];
    __shared__ float Bt[16][64];
    __shared__ float fb[16];
    int bx = blockIdx.x;           // n tile
    int by = blockIdx.y;           // m tile
    int bz = blockIdx.z;           // k split
    bool isBase = (by >= 12);
    if (isBase && bz >= 2) return;            // base rows only in planes 0,1
    bool doCvec = (by == 0);
    const float* Ap = isBase ? (pos + (by-12)*64*KD) : (d_acc + OFF_S + by*64*KD);
    const float* Bp = fcoutw + (isBase ? KD*DOUT : 0) + bx*64;
    int t  = threadIdx.x;
    int tx = t & 15;    // 4 cols
    int ty = t >> 4;    // 8 rows
    float acc[8][4];
    #pragma unroll
    for (int i = 0; i < 8; i++)
        #pragma unroll
        for (int j = 0; j < 4; j++) acc[i][j] = 0.f;
    float accC[4] = {0.f, 0.f, 0.f, 0.f};

    int arow = t >> 1;          // 0..63
    int koff = (t & 1) * 8;
    int bk   = t >> 4;          // 0..7 (and +8)
    int bn   = (t & 15) * 4;

    int kbeg = isBase ? bz*256 : bz*64;
    int kend = kbeg + (isBase ? 256 : 64);
    float4 ra0, ra1, rb0, rb1;
    ra0 = *(const float4*)&Ap[arow*KD + kbeg + koff];
    ra1 = *(const float4*)&Ap[arow*KD + kbeg + koff + 4];
    rb0 = *(const float4*)&Bp[(kbeg+bk  )*DOUT + bn];
    rb1 = *(const float4*)&Bp[(kbeg+bk+8)*DOUT + bn];

    for (int kc = kbeg; kc < kend; kc += 16) {
        At[koff+0][arow] = ra0.x; At[koff+1][arow] = ra0.y;
        At[koff+2][arow] = ra0.z; At[koff+3][arow] = ra0.w;
        At[koff+4][arow] = ra1.x; At[koff+5][arow] = ra1.y;
        At[koff+6][arow] = ra1.z; At[koff+7][arow] = ra1.w;
        *(float4*)&Bt[bk  ][bn] = rb0;
        *(float4*)&Bt[bk+8][bn] = rb1;
        if (doCvec && t < 16) fb[t] = fc1b[kc + t];
        __syncthreads();
        if (kc + 16 < kend) {            // prefetch next chunk
            ra0 = *(const float4*)&Ap[arow*KD + kc + 16 + koff];
            ra1 = *(const float4*)&Ap[arow*KD + kc + 16 + koff + 4];
            rb0 = *(const float4*)&Bp[(kc+16+bk  )*DOUT + bn];
            rb1 = *(const float4*)&Bp[(kc+16+bk+8)*DOUT + bn];
        }
        #pragma unroll
        for (int kk = 0; kk < 16; kk++) {
            float4 b4 = *(const float4*)&Bt[kk][tx*4];
            float4 aA = *(const float4*)&At[kk][ty*8];
            float4 aB = *(const float4*)&At[kk][ty*8 + 4];
            float av[8] = {aA.x,aA.y,aA.z,aA.w,aB.x,aB.y,aB.z,aB.w};
            float bv[4] = {b4.x,b4.y,b4.z,b4.w};
            if (doCvec) {
                float fbv = fb[kk];
                #pragma unroll
                for (int j = 0; j < 4; j++)
                    accC[j] = fmaf(fbv, bv[j], accC[j]);
            }
            #pragma unroll
            for (int i = 0; i < 8; i++)
                #pragma unroll
                for (int j = 0; j < 4; j++)
                    acc[i][j] = fmaf(av[i], bv[j], acc[i][j]);
        }
        __syncthreads();
    }

    int row0 = by*64 + ty*8;
    int col  = bx*64 + tx*4;
    if (doCvec && ty == 0) {
        if (bz == 0) {
            accC[0] += fcoutb[col];   accC[1] += fcoutb[col+1];
            accC[2] += fcoutb[col+2]; accC[3] += fcoutb[col+3];
        }
        float* cvp = d_acc + OFF_CV;
        #pragma unroll
        for (int j = 0; j < 4; j++)
            atomicAdd(&cvp[col + j], accC[j]);
    }
    float* S2 = d_acc + OFF_S2;
    #pragma unroll
    for (int i = 0; i < 8; i++)
        #pragma unroll
        for (int j = 0; j < 4; j++)
            atomicAdd(&S2[(row0+i)*DOUT + col + j], acc[i][j]);
}

// ---------------------------------------------------------------------------
// epilogue: out[bt,m,o] = VX*A0 + VY*A1 - V*AU + base[m,o] + cvec[o]
// Single-plane reads (RED-accumulated). 384 threads: warps 0-5 -> bt {0,1},
// warps 6-11 -> bt {2,3}. Base tile (16 m, +cvec) in 49 KB smem; A in regs.
// V scalars computed inline from coords. grid=(64 bt-quads, 16 m-tiles).
// ---------------------------------------------------------------------------
#define EPI_BT 4
#define EPI_M  16
#define EPI_THREADS 384
__global__ __launch_bounds__(EPI_THREADS, 3)
void epilogue_kernel(const float* __restrict__ coords,
                     const float* __restrict__ vis,
                     float* __restrict__ out) {
    extern __shared__ float4 sm[];
    float4* sBase = sm;                    // [EPI_M][192]
    float4* sVp   = sm + EPI_M*NF4;        // [EPI_M][EPI_BT] (vx, vy, v, 0)

    int bt0 = blockIdx.x * EPI_BT;
    int m0  = blockIdx.y * EPI_M;
    int t   = threadIdx.x;     // 0..383
    int w   = t >> 5, l = t & 31;
    int tcol = (w % 6)*32 + l;   // 0..191
    int bth  = w / 6;            // 0 or 1 (bt half)

    const float4* S2 = (const float4*)(d_acc + OFF_S2);

    float4 cv = ((const float4*)(d_acc + OFF_CV))[tcol];

    // stage base tile (+cvec); each bt-half stages 8 of the 16 rows
    #pragma unroll
    for (int k = 0; k < EPI_M/2; k++) {
        int mm = bth*(EPI_M/2) + k;
        float4 u = S2[(768 + m0 + mm)*NF4 + tcol];
        sBase[mm*NF4 + tcol] = make_float4(u.x+cv.x, u.y+cv.y, u.z+cv.z, u.w+cv.w);
    }
    // A rows: single plane -> registers (2 bt per thread)
    float4 a0[2], a1[2], au[2];
    #pragma unroll
    for (int i = 0; i < 2; i++) {
        int bt = bt0 + bth*2 + i;
        a0[i] = S2[(0*BT + bt)*NF4 + tcol];
        a1[i] = S2[(1*BT + bt)*NF4 + tcol];
        au[i] = S2[(2*BT + bt)*NF4 + tcol];
    }
    // V scalars inline from coords/vis
    if (t < EPI_M*EPI_BT) {
        int mm = t >> 2, bi = t & 3;
        int bt = bt0 + bi;
        int b = bt >> 6, tt = bt & 63;
        int ci = (b*Mm + (m0+mm))*Tt + tt;
        float x = coords[2*ci], y = coords[2*ci+1], v = vis[ci];
        if (is_nan_bits(x)) { v = 0.f; x = 0.f; }
        if (is_nan_bits(y)) { y = 0.f; }
        sVp[mm*EPI_BT + bi] = make_float4(x*v, y*v, v, 0.f);
    }
    __syncthreads();

    #pragma unroll 4
    for (int mm = 0; mm < EPI_M; mm++) {
        float4 bv = sBase[mm*NF4 + tcol];
        int m = m0 + mm;
        #pragma unroll
        for (int i = 0; i < 2; i++) {
            float4 vp = sVp[mm*EPI_BT + bth*2 + i];
            float4 o4;
            o4.x = fmaf(vp.x, a0[i].x, fmaf(vp.y, a1[i].x, fmaf(-vp.z, au[i].x, bv.x)));
            o4.y = fmaf(vp.x, a0[i].y, fmaf(vp.y, a1[i].y, fmaf(-vp.z, au[i].y, bv.y)));
            o4.z = fmaf(vp.x, a0[i].z, fmaf(vp.y, a1[i].z, fmaf(-vp.z, au[i].z, bv.z)));
            o4.w = fmaf(vp.x, a0[i].w, fmaf(vp.y, a1[i].w, fmaf(-vp.z, au[i].w, bv.w)));
            ((float4*)out)[((bt0 + bth*2 + i)*Mm + m)*NF4 + tcol] = o4;
        }
    }
}

// ---------------------------------------------------------------------------
extern "C" void kernel_launch(void* const* d_in, const int* in_sizes, int n_in,
                              void* d_out, int out_size) {
    const float* coords = (const float*)d_in[0];
    const float* vis    = (const float*)d_in[1];
    const float* pos    = (const float*)d_in[2];
    const float* fc1w   = (const float*)d_in[3];
    const float* fc1b   = (const float*)d_in[4];
    const float* fcoutw = (const float*)d_in[5];
    const float* fcoutb = (const float*)d_in[6];
    float* out = (float*)d_out;

    static int smem_set = 0;
    int epi_smem = EPI_M*NF4*16 + EPI_M*EPI_BT*16;   // 49152 + 1024 = 50,176 B
    if (!smem_set) {
        cudaFuncSetAttribute(epilogue_kernel,
                             cudaFuncAttributeMaxDynamicSharedMemorySize, epi_smem);
        smem_set = 1;
    }

    zero_kernel    <<<(TOTF/4 + 255)/256, 256>>>();
    stage1_kernel  <<<dim3(4,8,JSPLIT), 256>>>(coords, vis, fc1w);
    stage2_kernel  <<<dim3(12,16,KSPLIT), 128>>>(fcoutw, pos, fc1b, fcoutb);
    epilogue_kernel<<<dim3(BT/EPI_BT, Mm/EPI_M), EPI_THREADS, epi_smem>>>(coords, vis, out);
}